// round 1
// baseline (speedup 1.0000x reference)
#include <cuda_runtime.h>

// ---------------- problem constants (fixed shapes) ----------------
#define BATCH 4
#define NNODE 4096
#define NEDGE 65536
#define DIN   128
#define DBOND 64
#define DOUT  128
#define NT    4
#define DCAT  (2*DIN + DBOND)   // 320

// ---------------- tiling ----------------
#define TM 64      // edges per tile
#define TK 32      // K chunk
#define TB 256     // threads per block
#define MAX_TILES (NEDGE/TM + NT)   // 1028 (padding slack per type segment)
#define SA_STRIDE (TM + 1)          // 65: conflict-free sA
#define SH_STRIDE (DOUT + 2)        // 130: conflict-free sH, float2-aligned

// ---------------- device scratch (no allocations allowed) ----------------
__device__ int g_counts[NT];
__device__ int g_cursor[NT];
__device__ int g_poff[NT + 1];
__device__ int g_order[NEDGE + NT * TM];

typedef unsigned long long u64;

// packed f32x2 helpers (Blackwell FFMA2 — only reachable via PTX)
__device__ __forceinline__ u64 pk2(float v) {
    u64 r; asm("mov.b64 %0, {%1, %1};" : "=l"(r) : "f"(v)); return r;
}
__device__ __forceinline__ void fma2(u64 &d, u64 a, u64 b) {
    asm("fma.rn.f32x2 %0, %1, %2, %0;" : "+l"(d) : "l"(a), "l"(b));
}
__device__ __forceinline__ float2 up2(u64 v) {
    float2 f; asm("mov.b64 {%0, %1}, %2;" : "=f"(f.x), "=f"(f.y) : "l"(v)); return f;
}

// ---------------- prep kernels ----------------
__global__ void k_init(float* __restrict__ out, int n_out) {
    int i = blockIdx.x * blockDim.x + threadIdx.x;
    if (i < n_out) out[i] = 0.f;
    if (i < NEDGE + NT * TM) g_order[i] = -1;
    if (i < NT) { g_counts[i] = 0; g_cursor[i] = 0; }
}

__global__ void k_hist(const int* __restrict__ uc) {
    int e = blockIdx.x * blockDim.x + threadIdx.x;
    if (e < NEDGE) atomicAdd(&g_counts[uc[e]], 1);
}

__global__ void k_prefix() {
    int off = 0;
    for (int t = 0; t < NT; t++) {
        g_poff[t] = off;
        off += (g_counts[t] + TM - 1) / TM * TM;   // pad each segment to TM
    }
    g_poff[NT] = off;
}

__global__ void k_order(const int* __restrict__ uc) {
    int e = blockIdx.x * blockDim.x + threadIdx.x;
    if (e < NEDGE) {
        int t = uc[e];
        int pos = atomicAdd(&g_cursor[t], 1);
        g_order[g_poff[t] + pos] = e;
    }
}

// ---------------- inner GEMM chunk: 4 rows x 8 cols (as 4 f32x2 pairs) over TK ----------------
// Column mapping: thread tx owns u64 pairs {tx + 16j}, i.e. float cols {2tx+32j, 2tx+32j+1}.
// All LDS conflict-free by construction.
__device__ __forceinline__ void mma32(
    const float* a0, const float* a1, const float* a2, const float* a3, int astep,
    const u64* w, u64 acc[4][4])
{
#pragma unroll
    for (int k = 0; k < TK; ++k) {
        u64 w0 = w[0], w1 = w[16], w2 = w[32], w3 = w[48];
        u64 p0 = pk2(*a0), p1 = pk2(*a1), p2 = pk2(*a2), p3 = pk2(*a3);
        a0 += astep; a1 += astep; a2 += astep; a3 += astep;
        w += 64;
        fma2(acc[0][0], p0, w0); fma2(acc[0][1], p0, w1); fma2(acc[0][2], p0, w2); fma2(acc[0][3], p0, w3);
        fma2(acc[1][0], p1, w0); fma2(acc[1][1], p1, w1); fma2(acc[1][2], p1, w2); fma2(acc[1][3], p1, w3);
        fma2(acc[2][0], p2, w0); fma2(acc[2][1], p2, w1); fma2(acc[2][2], p2, w2); fma2(acc[2][3], p2, w3);
        fma2(acc[3][0], p3, w0); fma2(acc[3][1], p3, w1); fma2(acc[3][2], p3, w2); fma2(acc[3][3], p3, w3);
    }
}

// ---------------- fused per-tile kernel ----------------
// Block: 64 edges of ONE type, one batch. Two fused MLPs (2 layers each),
// sigmoid gate, atomic scatter into out[b, idx2, :].
__global__ void __launch_bounds__(TB, 2) k_fused(
    const float* __restrict__ sites, const float* __restrict__ bonds,
    const int*   __restrict__ idx1,  const int*   __restrict__ idx2,
    const float* __restrict__ W1a, const float* __restrict__ b1a,
    const float* __restrict__ W1b, const float* __restrict__ b1b,
    const float* __restrict__ W2a, const float* __restrict__ b2a,
    const float* __restrict__ W2b, const float* __restrict__ b2b,
    const float* __restrict__ Wa1, const float* __restrict__ ba1,
    const float* __restrict__ Wa2, const float* __restrict__ ba2,
    float* __restrict__ out)
{
    extern __shared__ float sm[];
    float* sA = sm;                               // [TK][SA_STRIDE]
    float* sW = sA + TK * SA_STRIDE;              // [TK][DOUT]
    float* sH = sW + TK * DOUT;                   // [TM][SH_STRIDE]
    int*   sE  = (int*)(sH + TM * SH_STRIDE);
    int*   sI1 = sE + TM;
    int*   sI2 = sI1 + TM;

    const int tile  = blockIdx.x;
    const int b     = blockIdx.y;
    const int start = tile * TM;
    if (start >= g_poff[NT]) return;
    int t = 0;
#pragma unroll
    for (int i = 1; i < NT; i++) if (start >= g_poff[i]) t = i;

    const int tid = threadIdx.x;
    const int tx  = tid & 15;
    const int ty  = tid >> 4;

    if (tid < TM) {
        int e = g_order[start + tid];
        sE[tid] = e;
        int es = e < 0 ? 0 : e;
        sI1[tid] = idx1[es];
        sI2[tid] = idx2[es];
    }

    float gsum[4][8];
    const u64* wbase = (const u64*)sW + tx;

    for (int p = 0; p < 2; p++) {
        const float* Wla = (p ? W2a : W1a) + t * DCAT * DOUT;
        const float* bla = (p ? b2a : b1a) + t * DOUT;
        const float* Wlb = (p ? W2b : W1b) + t * DOUT * DOUT;
        const float* blb = (p ? b2b : b1b) + t * DOUT;
        const float* Wg  = p ? Wa2 : Wa1;
        const float  bg  = p ? ba2[0] : ba1[0];

        u64 acc[4][4];
#pragma unroll
        for (int r = 0; r < 4; r++)
#pragma unroll
            for (int j = 0; j < 4; j++) acc[r][j] = 0ull;

        // ---- layer A: [64 x DCAT] @ [DCAT x 128] ----
        for (int kc = 0; kc < DCAT; kc += TK) {
            __syncthreads();
            // stage gathered A chunk: A[row][k] -> sA[k][row]
#pragma unroll
            for (int i = 0; i < 2; i++) {
                int lin = tid + TB * i;            // 0..511 = 64 rows x 8 float4
                int row = lin >> 3;
                int f4  = (lin & 7) * 4;
                const float* src;
                if (kc < DIN) {
                    src = sites + ((size_t)b * NNODE + sI1[row]) * DIN + kc;
                } else if (kc < 2 * DIN) {
                    src = sites + ((size_t)b * NNODE + sI2[row]) * DIN + (kc - DIN);
                } else {
                    int e = sE[row]; if (e < 0) e = 0;
                    src = bonds + ((size_t)b * NEDGE + e) * DBOND + (kc - 2 * DIN);
                }
                float4 v = *(const float4*)(src + f4);
                sA[(f4 + 0) * SA_STRIDE + row] = v.x;
                sA[(f4 + 1) * SA_STRIDE + row] = v.y;
                sA[(f4 + 2) * SA_STRIDE + row] = v.z;
                sA[(f4 + 3) * SA_STRIDE + row] = v.w;
            }
            // stage W chunk [TK][128]
            const float4* ws = (const float4*)(Wla + kc * DOUT);
            float4* wd = (float4*)sW;
#pragma unroll
            for (int j = 0; j < 4; j++) { int lin = tid + TB * j; wd[lin] = ws[lin]; }
            __syncthreads();
            mma32(sA + ty * 4 + 0, sA + ty * 4 + 1, sA + ty * 4 + 2, sA + ty * 4 + 3,
                  SA_STRIDE, wbase, acc);
        }

        // h = lrelu(acc + bias) -> sH
#pragma unroll
        for (int r = 0; r < 4; r++) {
            int row = ty * 4 + r;
#pragma unroll
            for (int j = 0; j < 4; j++) {
                int c = 2 * tx + 32 * j;
                float2 v = up2(acc[r][j]);
                float h0 = v.x + bla[c];
                float h1 = v.y + bla[c + 1];
                h0 = h0 > 0.f ? h0 : 0.01f * h0;
                h1 = h1 > 0.f ? h1 : 0.01f * h1;
                *(float2*)&sH[row * SH_STRIDE + c] = make_float2(h0, h1);
            }
        }
#pragma unroll
        for (int r = 0; r < 4; r++)
#pragma unroll
            for (int j = 0; j < 4; j++) acc[r][j] = 0ull;
        __syncthreads();   // sH visible to all before layer B

        // ---- layer B: [64 x 128] @ [128 x 128] ----
        for (int kc = 0; kc < DOUT; kc += TK) {
            __syncthreads();
            const float4* ws = (const float4*)(Wlb + kc * DOUT);
            float4* wd = (float4*)sW;
#pragma unroll
            for (int j = 0; j < 4; j++) { int lin = tid + TB * j; wd[lin] = ws[lin]; }
            __syncthreads();
            const float* hb = sH + kc;
            mma32(hb + (ty * 4 + 0) * SH_STRIDE, hb + (ty * 4 + 1) * SH_STRIDE,
                  hb + (ty * 4 + 2) * SH_STRIDE, hb + (ty * 4 + 3) * SH_STRIDE,
                  1, wbase, acc);
        }

        // ---- out = lrelu(acc + blb); gate = sigmoid(out . Wg + bg) ----
        float dot[4];
#pragma unroll
        for (int r = 0; r < 4; r++) {
            float s = 0.f;
#pragma unroll
            for (int j = 0; j < 4; j++) {
                int c = 2 * tx + 32 * j;
                float2 v = up2(acc[r][j]);
                float o0 = v.x + blb[c];     o0 = o0 > 0.f ? o0 : 0.01f * o0;
                float o1 = v.y + blb[c + 1]; o1 = o1 > 0.f ? o1 : 0.01f * o1;
                s += o0 * Wg[c] + o1 * Wg[c + 1];
            }
            // reduce across the 16 tx lanes sharing this ty (xor<16 stays in-half)
#pragma unroll
            for (int m = 1; m < 16; m <<= 1) s += __shfl_xor_sync(0xffffffffu, s, m);
            dot[r] = s;
        }
#pragma unroll
        for (int r = 0; r < 4; r++) {
            float sig = 1.f / (1.f + __expf(-(dot[r] + bg)));
#pragma unroll
            for (int j = 0; j < 4; j++) {
                int c = 2 * tx + 32 * j;
                float2 v = up2(acc[r][j]);
                float o0 = v.x + blb[c];     o0 = o0 > 0.f ? o0 : 0.01f * o0;
                float o1 = v.y + blb[c + 1]; o1 = o1 > 0.f ? o1 : 0.01f * o1;
                if (p == 0) { gsum[r][2 * j] = sig * o0;  gsum[r][2 * j + 1] = sig * o1; }
                else        { gsum[r][2 * j] += sig * o0; gsum[r][2 * j + 1] += sig * o1; }
            }
        }
    } // p

    // ---- scatter-add g1+g2 into out[b, idx2, :] ----
#pragma unroll
    for (int r = 0; r < 4; r++) {
        int row = ty * 4 + r;
        int e = sE[row];
        if (e < 0) continue;
        float* dst = out + ((size_t)b * NNODE + sI2[row]) * DOUT;
#pragma unroll
        for (int j = 0; j < 4; j++) {
            int c = 2 * tx + 32 * j;
            atomicAdd(dst + c,     gsum[r][2 * j]);
            atomicAdd(dst + c + 1, gsum[r][2 * j + 1]);
        }
    }
}

// ---------------- launcher ----------------
extern "C" void kernel_launch(void* const* d_in, const int* in_sizes, int n_in,
                              void* d_out, int out_size) {
    (void)in_sizes; (void)n_in;
    const float* sites = (const float*)d_in[0];
    const float* bonds = (const float*)d_in[1];
    const int*   idx1  = (const int*)d_in[2];
    const int*   idx2  = (const int*)d_in[3];
    const int*   uc    = (const int*)d_in[4];
    const float* W1a = (const float*)d_in[5];
    const float* b1a = (const float*)d_in[6];
    const float* W1b = (const float*)d_in[7];
    const float* b1b = (const float*)d_in[8];
    const float* W2a = (const float*)d_in[9];
    const float* b2a = (const float*)d_in[10];
    const float* W2b = (const float*)d_in[11];
    const float* b2b = (const float*)d_in[12];
    const float* Wa1 = (const float*)d_in[13];
    const float* ba1 = (const float*)d_in[14];
    const float* Wa2 = (const float*)d_in[15];
    const float* ba2 = (const float*)d_in[16];
    float* out = (float*)d_out;

    const int smem = (TK * SA_STRIDE + TK * DOUT + TM * SH_STRIDE) * (int)sizeof(float)
                   + 3 * TM * (int)sizeof(int);
    cudaFuncSetAttribute(k_fused, cudaFuncAttributeMaxDynamicSharedMemorySize, smem);

    k_init<<<(out_size + TB - 1) / TB, TB>>>(out, out_size);
    k_hist<<<NEDGE / TB, TB>>>(uc);
    k_prefix<<<1, 1>>>();
    k_order<<<NEDGE / TB, TB>>>(uc);

    dim3 grid(MAX_TILES, BATCH);
    k_fused<<<grid, TB, smem>>>(sites, bonds, idx1, idx2,
                                W1a, b1a, W1b, b1b, W2a, b2a, W2b, b2b,
                                Wa1, ba1, Wa2, ba2, out);
}

// round 3
// speedup vs baseline: 2.2209x; 2.2209x over previous
#include <cuda_runtime.h>
#include <cstdint>

// ---------------- problem constants ----------------
#define BATCH 4
#define NNODE 4096
#define NEDGE 65536
#define DIN   128
#define DBOND 64
#define DOUT  128
#define NT    4
#define DCAT  320

#define TM    128
#define TB    256
#define NCH_A 10
#define NCH_B 4
#define WSTR  136                  // W smem row stride (floats) -> conflict-free B frags
#define WTILE (32*WSTR)            // 4352 floats per W chunk tile
#define ASTR  36                   // A staging stride -> conflict-free A frags
#define HSTR  132                  // H / G stride
#define MAX_TILES (NEDGE/TM + NT)  // 516

// ---------------- device scratch ----------------
__device__ int g_counts[NT];
__device__ int g_cursor[NT];
__device__ int g_poff[NT + 1];
__device__ int g_order[NEDGE + NT * TM];
__device__ float g_WA[2 * NT * NCH_A * WTILE];
__device__ float g_WB[2 * NT * NCH_B * WTILE];

// ---------------- helpers ----------------
__device__ __forceinline__ uint32_t f2t(float f) {
    uint32_t u; asm("cvt.rna.tf32.f32 %0, %1;" : "=r"(u) : "f"(f)); return u;
}
__device__ __forceinline__ float lrelu(float x) { return x > 0.f ? x : 0.01f * x; }

__device__ __forceinline__ void mma8(float* d, uint32_t a0, uint32_t a1, uint32_t a2, uint32_t a3,
                                     uint32_t b0, uint32_t b1) {
    asm volatile(
        "mma.sync.aligned.m16n8k8.row.col.f32.tf32.tf32.f32 "
        "{%0,%1,%2,%3},{%4,%5,%6,%7},{%8,%9},{%0,%1,%2,%3};"
        : "+f"(d[0]), "+f"(d[1]), "+f"(d[2]), "+f"(d[3])
        : "r"(a0), "r"(a1), "r"(a2), "r"(a3), "r"(b0), "r"(b1));
}

// ---------------- prep kernels ----------------
__global__ void k_init(float* __restrict__ out, int n_out) {
    int i = blockIdx.x * blockDim.x + threadIdx.x;
    if (i < n_out) out[i] = 0.f;
    if (i < NEDGE + NT * TM) g_order[i] = -1;
    if (i < NT) { g_counts[i] = 0; g_cursor[i] = 0; }
}
__global__ void k_hist(const int* __restrict__ uc) {
    int e = blockIdx.x * blockDim.x + threadIdx.x;
    if (e < NEDGE) atomicAdd(&g_counts[uc[e]], 1);
}
__global__ void k_prefix() {
    int off = 0;
    for (int t = 0; t < NT; t++) {
        g_poff[t] = off;
        off += (g_counts[t] + TM - 1) / TM * TM;
    }
    g_poff[NT] = off;
}
__global__ void k_order(const int* __restrict__ uc) {
    int e = blockIdx.x * blockDim.x + threadIdx.x;
    if (e < NEDGE) {
        int t = uc[e];
        int pos = atomicAdd(&g_cursor[t], 1);
        g_order[g_poff[t] + pos] = e;
    }
}

// Transpose weights to padded [k][n] chunk tiles, tf32-converted.
__global__ void k_prepw(const float* __restrict__ W1a, const float* __restrict__ W2a,
                        const float* __restrict__ W1b, const float* __restrict__ W2b) {
    int i = blockIdx.x * blockDim.x + threadIdx.x;
    const int NA = 2 * NT * NCH_A * 4096;
    const int NB = 2 * NT * NCH_B * 4096;
    if (i < NA) {
        int n = i & 127, k = (i >> 7) & 31;
        int tileIdx = i >> 12;
        int c = tileIdx % NCH_A, pt = tileIdx / NCH_A;
        int t = pt & 3, p = pt >> 2;
        const float* W = p ? W2a : W1a;
        float v = W[((size_t)t * DCAT + (c * 32 + k)) * DOUT + n];
        g_WA[(size_t)tileIdx * WTILE + k * WSTR + n] = __uint_as_float(f2t(v));
    } else if (i < NA + NB) {
        int j = i - NA;
        int n = j & 127, k = (j >> 7) & 31;
        int tileIdx = j >> 12;
        int c = tileIdx & 3, pt = tileIdx >> 2;
        int t = pt & 3, p = pt >> 2;
        const float* W = p ? W2b : W1b;
        float v = W[((size_t)t * DOUT + (c * 32 + k)) * DOUT + n];
        g_WB[(size_t)tileIdx * WTILE + k * WSTR + n] = __uint_as_float(f2t(v));
    }
}

// ---------------- gather helper ----------------
__device__ __forceinline__ float4 gatherA(const float* __restrict__ sites,
                                          const float* __restrict__ bonds, int b,
                                          const int* sE, const int* sI1, const int* sI2,
                                          int lin, int kc) {
    int row = lin >> 3;
    int col = (lin & 7) << 2;
    const float* src;
    if (kc < 128)       src = sites + ((size_t)b * NNODE + sI1[row]) * DIN + kc + col;
    else if (kc < 256)  src = sites + ((size_t)b * NNODE + sI2[row]) * DIN + (kc - 128) + col;
    else { int e = sE[row]; if (e < 0) e = 0;
           src = bonds + ((size_t)b * NEDGE + e) * DBOND + (kc - 256) + col; }
    return *(const float4*)src;
}

// ---------------- smem layout (float offsets) ----------------
#define OF_U    0        // 16896 : A-staging (2x4608) then H [128][132]
#define OF_G    16896    // 16896 : g1 buffer [128][132]
#define OF_W    33792    // 8704  : W double buffer (2 x 4352)
#define OF_RED  42496    // 128
#define OF_BLA  42624
#define OF_BLB  42752
#define OF_WG   42880
#define OF_E    43008
#define OF_I1   43136
#define OF_I2   43264
#define SMEM_FLOATS 43392
#define SMEM_BYTES (SMEM_FLOATS * 4)

// ---------------- main fused kernel ----------------
__global__ void __launch_bounds__(TB, 1) k_fused(
    const float* __restrict__ sites, const float* __restrict__ bonds,
    const int* __restrict__ idx1, const int* __restrict__ idx2,
    const float* __restrict__ b1a, const float* __restrict__ b1b,
    const float* __restrict__ b2a, const float* __restrict__ b2b,
    const float* __restrict__ Wa1, const float* __restrict__ ba1,
    const float* __restrict__ Wa2, const float* __restrict__ ba2,
    float* __restrict__ out)
{
    extern __shared__ float sm[];
    float* U    = sm + OF_U;
    float* sG   = sm + OF_G;
    float* sW   = sm + OF_W;
    float* sRed = sm + OF_RED;
    float* sBla = sm + OF_BLA;
    float* sBlb = sm + OF_BLB;
    float* sWg  = sm + OF_WG;
    int* sE  = (int*)(sm + OF_E);
    int* sI1 = (int*)(sm + OF_I1);
    int* sI2 = (int*)(sm + OF_I2);

    const int tile  = blockIdx.x;
    const int b     = blockIdx.y;
    const int start = tile * TM;
    if (start >= g_poff[NT]) return;
    int t = 0;
#pragma unroll
    for (int i = 1; i < NT; i++) if (start >= g_poff[i]) t = i;

    const int tid  = threadIdx.x;
    const int lane = tid & 31;
    const int wid  = tid >> 5;
    const int wm   = wid & 1;       // 0..1 : 64-row half
    const int wn   = wid >> 1;      // 0..3 : 32-col quarter
    const int grp  = lane >> 2;     // 0..7
    const int qq   = lane & 3;      // 0..3

    if (tid < TM) {
        int e = g_order[start + tid];
        sE[tid] = e;
        int es = e < 0 ? 0 : e;
        sI1[tid] = idx1[es];
        sI2[tid] = idx2[es];
    }
    __syncthreads();

    for (int p = 0; p < 2; p++) {
        __syncthreads();   // protect biases / sG from previous-phase readers
        {
            const float* bla = (p ? b2a : b1a) + t * DOUT;
            const float* blb = (p ? b2b : b1b) + t * DOUT;
            const float* wg  = p ? Wa2 : Wa1;
            if (tid < 128) { sBla[tid] = bla[tid]; sBlb[tid] = blb[tid]; sWg[tid] = wg[tid]; }
        }
        const float bg = p ? ba2[0] : ba1[0];
        const float* gWA = g_WA + (size_t)((p * NT + t) * NCH_A) * WTILE;
        const float* gWB = g_WB + (size_t)((p * NT + t) * NCH_B) * WTILE;

        float acc[4][4][4];
#pragma unroll
        for (int mt = 0; mt < 4; mt++)
#pragma unroll
            for (int nt = 0; nt < 4; nt++)
#pragma unroll
                for (int i = 0; i < 4; i++) acc[mt][nt][i] = 0.f;

        // ================= layer A =================
        float4 pA[4], pW[4];
#pragma unroll
        for (int i = 0; i < 4; i++) {
            pA[i] = gatherA(sites, bonds, b, sE, sI1, sI2, tid + TB * i, 0);
            int lin = tid + TB * i;
            pW[i] = *(const float4*)(gWA + (lin >> 5) * WSTR + ((lin & 31) << 2));
        }
        for (int c = 0; c < NCH_A; c++) {
            const int s = c & 1;
            float* Ab = U + s * (TM * ASTR);
            float* Wb = sW + s * WTILE;
#pragma unroll
            for (int i = 0; i < 4; i++) {
                int lin = tid + TB * i;
                int row = lin >> 3, c4 = (lin & 7) << 2;
                float4 o;
                o.x = __uint_as_float(f2t(pA[i].x));
                o.y = __uint_as_float(f2t(pA[i].y));
                o.z = __uint_as_float(f2t(pA[i].z));
                o.w = __uint_as_float(f2t(pA[i].w));
                *(float4*)(Ab + row * ASTR + c4) = o;
                *(float4*)(Wb + (lin >> 5) * WSTR + ((lin & 31) << 2)) = pW[i];
            }
            __syncthreads();
            if (c + 1 < NCH_A) {
                const float* gWc = gWA + (size_t)(c + 1) * WTILE;
#pragma unroll
                for (int i = 0; i < 4; i++) {
                    int lin = tid + TB * i;
                    pA[i] = gatherA(sites, bonds, b, sE, sI1, sI2, lin, (c + 1) * 32);
                    pW[i] = *(const float4*)(gWc + (lin >> 5) * WSTR + ((lin & 31) << 2));
                }
            }
            const uint32_t* A32 = (const uint32_t*)Ab;
            const uint32_t* W32 = (const uint32_t*)Wb;
#pragma unroll
            for (int kk = 0; kk < 4; kk++) {
                const int kb = kk * 8;
                uint32_t bf0[4], bf1[4];
#pragma unroll
                for (int nt = 0; nt < 4; nt++) {
                    int ncol = wn * 32 + nt * 8 + grp;
                    bf0[nt] = W32[(kb + qq) * WSTR + ncol];
                    bf1[nt] = W32[(kb + 4 + qq) * WSTR + ncol];
                }
#pragma unroll
                for (int mt = 0; mt < 4; mt++) {
                    int r = wm * 64 + mt * 16 + grp;
                    uint32_t a0 = A32[r * ASTR + kb + qq];
                    uint32_t a1 = A32[(r + 8) * ASTR + kb + qq];
                    uint32_t a2 = A32[r * ASTR + kb + 4 + qq];
                    uint32_t a3 = A32[(r + 8) * ASTR + kb + 4 + qq];
#pragma unroll
                    for (int nt = 0; nt < 4; nt++)
                        mma8(acc[mt][nt], a0, a1, a2, a3, bf0[nt], bf1[nt]);
                }
            }
        }
        __syncthreads();   // all A-buffer reads done before H overwrite

        // ---- epilogue A: H = tf32(lrelu(acc + bla)) -> U [128][HSTR] ----
#pragma unroll
        for (int mt = 0; mt < 4; mt++) {
            int r = wm * 64 + mt * 16 + grp;
#pragma unroll
            for (int nt = 0; nt < 4; nt++) {
                int cc = wn * 32 + nt * 8 + 2 * qq;
                float h0 = lrelu(acc[mt][nt][0] + sBla[cc]);
                float h1 = lrelu(acc[mt][nt][1] + sBla[cc + 1]);
                float h2 = lrelu(acc[mt][nt][2] + sBla[cc]);
                float h3 = lrelu(acc[mt][nt][3] + sBla[cc + 1]);
                U[r * HSTR + cc]           = __uint_as_float(f2t(h0));
                U[r * HSTR + cc + 1]       = __uint_as_float(f2t(h1));
                U[(r + 8) * HSTR + cc]     = __uint_as_float(f2t(h2));
                U[(r + 8) * HSTR + cc + 1] = __uint_as_float(f2t(h3));
#pragma unroll
                for (int i = 0; i < 4; i++) acc[mt][nt][i] = 0.f;
            }
        }
        __syncthreads();

        // ================= layer B =================
#pragma unroll
        for (int i = 0; i < 4; i++) {
            int lin = tid + TB * i;
            pW[i] = *(const float4*)(gWB + (lin >> 5) * WSTR + ((lin & 31) << 2));
        }
        for (int c = 0; c < NCH_B; c++) {
            const int s = c & 1;
            float* Wb = sW + s * WTILE;
#pragma unroll
            for (int i = 0; i < 4; i++) {
                int lin = tid + TB * i;
                *(float4*)(Wb + (lin >> 5) * WSTR + ((lin & 31) << 2)) = pW[i];
            }
            __syncthreads();
            if (c + 1 < NCH_B) {
                const float* gWc = gWB + (size_t)(c + 1) * WTILE;
#pragma unroll
                for (int i = 0; i < 4; i++) {
                    int lin = tid + TB * i;
                    pW[i] = *(const float4*)(gWc + (lin >> 5) * WSTR + ((lin & 31) << 2));
                }
            }
            const uint32_t* H32 = (const uint32_t*)U;
            const uint32_t* W32 = (const uint32_t*)Wb;
#pragma unroll
            for (int kk = 0; kk < 4; kk++) {
                const int kb = kk * 8;
                const int kg = c * 32 + kb;
                uint32_t bf0[4], bf1[4];
#pragma unroll
                for (int nt = 0; nt < 4; nt++) {
                    int ncol = wn * 32 + nt * 8 + grp;
                    bf0[nt] = W32[(kb + qq) * WSTR + ncol];
                    bf1[nt] = W32[(kb + 4 + qq) * WSTR + ncol];
                }
#pragma unroll
                for (int mt = 0; mt < 4; mt++) {
                    int r = wm * 64 + mt * 16 + grp;
                    uint32_t a0 = H32[r * HSTR + kg + qq];
                    uint32_t a1 = H32[(r + 8) * HSTR + kg + qq];
                    uint32_t a2 = H32[r * HSTR + kg + 4 + qq];
                    uint32_t a3 = H32[(r + 8) * HSTR + kg + 4 + qq];
#pragma unroll
                    for (int nt = 0; nt < 4; nt++)
                        mma8(acc[mt][nt], a0, a1, a2, a3, bf0[nt], bf1[nt]);
                }
            }
        }
        __syncthreads();
        if (tid < 128) sRed[tid] = 0.f;
        __syncthreads();

        // ---- gate dot: sRed[row] = sum_c lrelu(o)*Wg ----
#pragma unroll
        for (int mt = 0; mt < 4; mt++) {
            int r = wm * 64 + mt * 16 + grp;
            float d0 = 0.f, d1 = 0.f;
#pragma unroll
            for (int nt = 0; nt < 4; nt++) {
                int cc = wn * 32 + nt * 8 + 2 * qq;
                float w0 = sWg[cc], w1 = sWg[cc + 1];
                d0 += lrelu(acc[mt][nt][0] + sBlb[cc]) * w0
                    + lrelu(acc[mt][nt][1] + sBlb[cc + 1]) * w1;
                d1 += lrelu(acc[mt][nt][2] + sBlb[cc]) * w0
                    + lrelu(acc[mt][nt][3] + sBlb[cc + 1]) * w1;
            }
            d0 += __shfl_xor_sync(0xffffffffu, d0, 1);
            d0 += __shfl_xor_sync(0xffffffffu, d0, 2);
            d1 += __shfl_xor_sync(0xffffffffu, d1, 1);
            d1 += __shfl_xor_sync(0xffffffffu, d1, 2);
            if (qq == 0) {
                atomicAdd(&sRed[r], d0);
                atomicAdd(&sRed[r + 8], d1);
            }
        }
        __syncthreads();

        // ---- apply gate; p==0: store g1; p==1: combine + scatter ----
#pragma unroll
        for (int mt = 0; mt < 4; mt++) {
            int r = wm * 64 + mt * 16 + grp;
            float sig0 = 1.f / (1.f + __expf(-(sRed[r] + bg)));
            float sig1 = 1.f / (1.f + __expf(-(sRed[r + 8] + bg)));
            if (p == 0) {
#pragma unroll
                for (int nt = 0; nt < 4; nt++) {
                    int cc = wn * 32 + nt * 8 + 2 * qq;
                    sG[r * HSTR + cc]           = sig0 * lrelu(acc[mt][nt][0] + sBlb[cc]);
                    sG[r * HSTR + cc + 1]       = sig0 * lrelu(acc[mt][nt][1] + sBlb[cc + 1]);
                    sG[(r + 8) * HSTR + cc]     = sig1 * lrelu(acc[mt][nt][2] + sBlb[cc]);
                    sG[(r + 8) * HSTR + cc + 1] = sig1 * lrelu(acc[mt][nt][3] + sBlb[cc + 1]);
                }
            } else {
                bool v0 = sE[r] >= 0, v1 = sE[r + 8] >= 0;
                float* d0p = out + ((size_t)b * NNODE + sI2[r]) * DOUT;
                float* d1p = out + ((size_t)b * NNODE + sI2[r + 8]) * DOUT;
#pragma unroll
                for (int nt = 0; nt < 4; nt++) {
                    int cc = wn * 32 + nt * 8 + 2 * qq;
                    if (v0) {
                        atomicAdd(d0p + cc,     sig0 * lrelu(acc[mt][nt][0] + sBlb[cc])     + sG[r * HSTR + cc]);
                        atomicAdd(d0p + cc + 1, sig0 * lrelu(acc[mt][nt][1] + sBlb[cc + 1]) + sG[r * HSTR + cc + 1]);
                    }
                    if (v1) {
                        atomicAdd(d1p + cc,     sig1 * lrelu(acc[mt][nt][2] + sBlb[cc])     + sG[(r + 8) * HSTR + cc]);
                        atomicAdd(d1p + cc + 1, sig1 * lrelu(acc[mt][nt][3] + sBlb[cc + 1]) + sG[(r + 8) * HSTR + cc + 1]);
                    }
                }
            }
        }
    } // p
}

// ---------------- launcher ----------------
extern "C" void kernel_launch(void* const* d_in, const int* in_sizes, int n_in,
                              void* d_out, int out_size) {
    (void)in_sizes; (void)n_in;
    const float* sites = (const float*)d_in[0];
    const float* bonds = (const float*)d_in[1];
    const int*   idx1  = (const int*)d_in[2];
    const int*   idx2  = (const int*)d_in[3];
    const int*   uc    = (const int*)d_in[4];
    const float* W1a = (const float*)d_in[5];
    const float* b1a = (const float*)d_in[6];
    const float* W1b = (const float*)d_in[7];
    const float* b1b = (const float*)d_in[8];
    const float* W2a = (const float*)d_in[9];
    const float* b2a = (const float*)d_in[10];
    const float* W2b = (const float*)d_in[11];
    const float* b2b = (const float*)d_in[12];
    const float* Wa1 = (const float*)d_in[13];
    const float* ba1 = (const float*)d_in[14];
    const float* Wa2 = (const float*)d_in[15];
    const float* ba2 = (const float*)d_in[16];
    float* out = (float*)d_out;

    cudaFuncSetAttribute(k_fused, cudaFuncAttributeMaxDynamicSharedMemorySize, SMEM_BYTES);

    k_init<<<(out_size + TB - 1) / TB, TB>>>(out, out_size);
    k_hist<<<NEDGE / TB, TB>>>(uc);
    k_prefix<<<1, 1>>>();
    k_order<<<NEDGE / TB, TB>>>(uc);
    {
        const int total = 2 * NT * NCH_A * 4096 + 2 * NT * NCH_B * 4096;
        k_prepw<<<(total + TB - 1) / TB, TB>>>(W1a, W2a, W1b, W2b);
    }
    dim3 grid(MAX_TILES, BATCH);
    k_fused<<<grid, TB, SMEM_BYTES>>>(sites, bonds, idx1, idx2,
                                      b1a, b1b, b2a, b2b,
                                      Wa1, ba1, Wa2, ba2, out);
}

// round 4
// speedup vs baseline: 3.5898x; 1.6164x over previous
#include <cuda_runtime.h>
#include <cuda_fp16.h>
#include <cstdint>

// ---------------- problem constants ----------------
#define BATCH 4
#define NNODE 4096
#define NEDGE 65536
#define DIN   128
#define DBOND 64
#define DOUT  128
#define NT    4
#define DCAT  320

#define TM    128
#define TB    256
#define NCH_A 5                    // k-chunks of 64
#define NCH_B 2
#define WSTR2 36                   // W tile row stride in half2 (u32) units
#define WTILE (128*WSTR2)          // 4608 u32 per chunk tile
#define ASTR2 36                   // A staging stride (half2 units)
#define HSTR2 68                   // H stride (half2 units)
#define MAX_TILES (NEDGE/TM + NT)  // 516

// ---------------- device scratch ----------------
__device__ int g_counts[NT];
__device__ int g_cursor[NT];
__device__ int g_poff[NT + 1];
__device__ int g_order[NEDGE + NT * TM];
__device__ uint32_t g_WAh[2 * NT * NCH_A * WTILE];   // half2-packed, transposed, padded
__device__ uint32_t g_WBh[2 * NT * NCH_B * WTILE];

// ---------------- helpers ----------------
__device__ __forceinline__ float lrelu(float x) { return x > 0.f ? x : 0.01f * x; }
__device__ __forceinline__ uint32_t h2bits(float a, float b) {
    __half2 h = __floats2half2_rn(a, b);
    return *reinterpret_cast<uint32_t*>(&h);
}
__device__ __forceinline__ float2 h2f2(uint32_t u) {
    __half2 h = *reinterpret_cast<__half2*>(&u);
    return __half22float2(h);
}
__device__ __forceinline__ uint32_t smem_u32(const void* p) {
    uint32_t a;
    asm("{ .reg .u64 t; cvta.to.shared.u64 t, %1; cvt.u32.u64 %0, t; }" : "=r"(a) : "l"(p));
    return a;
}
__device__ __forceinline__ void cpasync16(uint32_t saddr, const void* g) {
    asm volatile("cp.async.ca.shared.global [%0], [%1], 16;" :: "r"(saddr), "l"(g));
}
#define CP_COMMIT() asm volatile("cp.async.commit_group;" ::: "memory")
#define CP_WAIT0()  asm volatile("cp.async.wait_group 0;" ::: "memory")

__device__ __forceinline__ void mma16(float* d, uint32_t a0, uint32_t a1, uint32_t a2, uint32_t a3,
                                      uint32_t b0, uint32_t b1) {
    asm volatile(
        "mma.sync.aligned.m16n8k16.row.col.f32.f16.f16.f32 "
        "{%0,%1,%2,%3},{%4,%5,%6,%7},{%8,%9},{%0,%1,%2,%3};"
        : "+f"(d[0]), "+f"(d[1]), "+f"(d[2]), "+f"(d[3])
        : "r"(a0), "r"(a1), "r"(a2), "r"(a3), "r"(b0), "r"(b1));
}

// ---------------- prep kernels ----------------
__global__ void k_init(float* __restrict__ out, int n_out) {
    int i = blockIdx.x * blockDim.x + threadIdx.x;
    if (i < n_out) out[i] = 0.f;
    if (i < NEDGE + NT * TM) g_order[i] = -1;
    if (i < NT) { g_counts[i] = 0; g_cursor[i] = 0; }
}
__global__ void k_hist(const int* __restrict__ uc) {
    int e = blockIdx.x * blockDim.x + threadIdx.x;
    if (e < NEDGE) atomicAdd(&g_counts[uc[e]], 1);
}
__global__ void k_prefix() {
    int off = 0;
    for (int t = 0; t < NT; t++) {
        g_poff[t] = off;
        off += (g_counts[t] + TM - 1) / TM * TM;
    }
    g_poff[NT] = off;
}
__global__ void k_order(const int* __restrict__ uc) {
    int e = blockIdx.x * blockDim.x + threadIdx.x;
    if (e < NEDGE) {
        int t = uc[e];
        int pos = atomicAdd(&g_cursor[t], 1);
        g_order[g_poff[t] + pos] = e;
    }
}

// Transpose + fp16-pack weights into padded [n][k2] chunk tiles.
__global__ void k_prepw(const float* __restrict__ W1a, const float* __restrict__ W2a,
                        const float* __restrict__ W1b, const float* __restrict__ W2b) {
    int i = blockIdx.x * blockDim.x + threadIdx.x;
    const int NAT = 2 * NT * NCH_A * 4096;
    const int NBT = 2 * NT * NCH_B * 4096;
    if (i >= NAT + NBT) return;
    bool isA = i < NAT;
    int j = isA ? i : i - NAT;
    int k2 = j & 31;
    int n = (j >> 5) & 127;
    int tileIdx = j >> 12;
    int nch = isA ? NCH_A : NCH_B;
    int c = tileIdx % nch, pt = tileIdx / nch;
    int t = pt & 3, p = pt >> 2;
    int k = c * 64 + 2 * k2;
    const float* W = isA ? (p ? W2a : W1a) : (p ? W2b : W1b);
    int ld = isA ? DCAT : DOUT;
    float v0 = W[((size_t)t * ld + k) * DOUT + n];
    float v1 = W[((size_t)t * ld + k + 1) * DOUT + n];
    uint32_t* dst = isA ? g_WAh : g_WBh;
    dst[(size_t)tileIdx * WTILE + n * WSTR2 + k2] = h2bits(v0, v1);
}

// ---------------- smem layout (u32 units) ----------------
#define OF_A    0        // 2 x 4608 A staging; aliased by H [128][68] (8704)
#define OF_W    9216     // 2 x 4608 W tiles
#define OF_RED  18432
#define OF_BLA  18560
#define OF_BLB  18688
#define OF_WG   18816
#define OF_E    18944
#define OF_I1   19072
#define OF_I2   19200
#define SMEM_U32 19328
#define SMEM_BYTES (SMEM_U32 * 4)

// ---------------- main fused kernel ----------------
__global__ void __launch_bounds__(TB) k_fused(
    const float* __restrict__ sites, const float* __restrict__ bonds,
    const int* __restrict__ idx1, const int* __restrict__ idx2,
    const float* __restrict__ b1a, const float* __restrict__ b1b,
    const float* __restrict__ b2a, const float* __restrict__ b2b,
    const float* __restrict__ Wa1, const float* __restrict__ ba1,
    const float* __restrict__ Wa2, const float* __restrict__ ba2,
    float* __restrict__ out)
{
    extern __shared__ uint32_t sm[];
    uint32_t* U    = sm + OF_A;                 // A staging / H
    uint32_t* sW   = sm + OF_W;
    float* sRed = (float*)(sm + OF_RED);
    float* sBla = (float*)(sm + OF_BLA);
    float* sBlb = (float*)(sm + OF_BLB);
    float* sWg  = (float*)(sm + OF_WG);
    int* sE  = (int*)(sm + OF_E);
    int* sI1 = (int*)(sm + OF_I1);
    int* sI2 = (int*)(sm + OF_I2);
    const uint32_t sb = smem_u32(sm);

    const int tile  = blockIdx.x;
    const int b     = blockIdx.y;
    const int start = tile * TM;
    if (start >= g_poff[NT]) return;
    int t = 0;
#pragma unroll
    for (int i = 1; i < NT; i++) if (start >= g_poff[i]) t = i;

    const int tid  = threadIdx.x;
    const int lane = tid & 31;
    const int wid  = tid >> 5;
    const int wm   = wid & 1;
    const int wn   = wid >> 1;
    const int grp  = lane >> 2;
    const int qq   = lane & 3;

    if (tid < TM) {
        int e = g_order[start + tid];
        sE[tid] = e;
        int es = e < 0 ? 0 : e;
        sI1[tid] = idx1[es];
        sI2[tid] = idx2[es];
    }
    __syncthreads();

    uint32_t g1h[32];                 // phase-0 gated output (half2 pairs)

    for (int p = 0; p < 2; p++) {
        __syncthreads();
        {
            const float* bla = (p ? b2a : b1a) + t * DOUT;
            const float* blb = (p ? b2b : b1b) + t * DOUT;
            const float* wg  = p ? Wa2 : Wa1;
            if (tid < 128) { sBla[tid] = bla[tid]; sBlb[tid] = blb[tid]; sWg[tid] = wg[tid]; }
        }
        const float bg = p ? ba2[0] : ba1[0];
        const uint32_t* gWA = g_WAh + (size_t)((p * NT + t) * NCH_A) * WTILE;
        const uint32_t* gWB = g_WBh + (size_t)((p * NT + t) * NCH_B) * WTILE;

        float acc[4][4][4];
#pragma unroll
        for (int mt = 0; mt < 4; mt++)
#pragma unroll
            for (int nt = 0; nt < 4; nt++)
#pragma unroll
                for (int i = 0; i < 4; i++) acc[mt][nt][i] = 0.f;

        // ================= layer A =================
        float4 pA[8];
        // prologue: W chunk0 via cp.async, gather chunk0
        {
#pragma unroll
            for (int i = 0; i < 5; i++) {
                int lin = tid + TB * i;
                if (lin < 1152) cpasync16(sb + (OF_W + 0) * 4 + lin * 16, (const uint4*)gWA + lin);
            }
            CP_COMMIT();
        }
#pragma unroll
        for (int i = 0; i < 8; i++) {
            int lin = tid + TB * i;
            int row = lin >> 4, col = (lin & 15) << 2;
            pA[i] = *(const float4*)(sites + ((size_t)b * NNODE + sI1[row]) * DIN + col);
        }

        for (int c = 0; c < NCH_A; c++) {
            const int s = c & 1;
            uint32_t* Ab = U + s * 4608;
            // stage A chunk c (convert to half2)
#pragma unroll
            for (int i = 0; i < 8; i++) {
                int lin = tid + TB * i;
                int row = lin >> 4, j = (lin & 15) << 1;
                uint2 v;
                v.x = h2bits(pA[i].x, pA[i].y);
                v.y = h2bits(pA[i].z, pA[i].w);
                *(uint2*)(Ab + row * ASTR2 + j) = v;
            }
            CP_WAIT0();
            __syncthreads();
            if (c + 1 < NCH_A) {
                // issue W chunk c+1 into other buffer
                const uint4* gsrc = (const uint4*)(gWA + (size_t)(c + 1) * WTILE);
#pragma unroll
                for (int i = 0; i < 5; i++) {
                    int lin = tid + TB * i;
                    if (lin < 1152) cpasync16(sb + (OF_W + (s ^ 1) * 4608) * 4 + lin * 16, gsrc + lin);
                }
                CP_COMMIT();
                // gather A chunk c+1
                const int cn = c + 1;
#pragma unroll
                for (int i = 0; i < 8; i++) {
                    int lin = tid + TB * i;
                    int row = lin >> 4, col = (lin & 15) << 2;
                    const float* src;
                    if (cn < 2)      src = sites + ((size_t)b * NNODE + sI1[row]) * DIN + cn * 64 + col;
                    else if (cn < 4) src = sites + ((size_t)b * NNODE + sI2[row]) * DIN + (cn - 2) * 64 + col;
                    else { int e = sE[row]; if (e < 0) e = 0;
                           src = bonds + ((size_t)b * NEDGE + e) * DBOND + col; }
                    pA[i] = *(const float4*)src;
                }
            }
            // MMA on chunk c
            const uint32_t* A32 = Ab;
            const uint32_t* W32 = sW + s * 4608;
#pragma unroll
            for (int kk = 0; kk < 4; kk++) {
                const int kb = kk * 8;
                uint32_t bf0[4], bf1[4];
#pragma unroll
                for (int nt = 0; nt < 4; nt++) {
                    int ncol = wn * 32 + nt * 8 + grp;
                    bf0[nt] = W32[ncol * WSTR2 + kb + qq];
                    bf1[nt] = W32[ncol * WSTR2 + kb + 4 + qq];
                }
#pragma unroll
                for (int mt = 0; mt < 4; mt++) {
                    int r = wm * 64 + mt * 16 + grp;
                    uint32_t a0 = A32[r * ASTR2 + kb + qq];
                    uint32_t a1 = A32[(r + 8) * ASTR2 + kb + qq];
                    uint32_t a2 = A32[r * ASTR2 + kb + 4 + qq];
                    uint32_t a3 = A32[(r + 8) * ASTR2 + kb + 4 + qq];
#pragma unroll
                    for (int nt = 0; nt < 4; nt++)
                        mma16(acc[mt][nt], a0, a1, a2, a3, bf0[nt], bf1[nt]);
                }
            }
        }
        __syncthreads();   // all layer-A MMA done; A buffers free

        // ---- epilogue A: H = fp16(lrelu(acc + bla)) into U ----
#pragma unroll
        for (int mt = 0; mt < 4; mt++) {
            int r = wm * 64 + mt * 16 + grp;
#pragma unroll
            for (int nt = 0; nt < 4; nt++) {
                int cc = wn * 32 + nt * 8 + 2 * qq;
                int col2 = wn * 16 + nt * 4 + qq;
                U[r * HSTR2 + col2] =
                    h2bits(lrelu(acc[mt][nt][0] + sBla[cc]), lrelu(acc[mt][nt][1] + sBla[cc + 1]));
                U[(r + 8) * HSTR2 + col2] =
                    h2bits(lrelu(acc[mt][nt][2] + sBla[cc]), lrelu(acc[mt][nt][3] + sBla[cc + 1]));
#pragma unroll
                for (int i = 0; i < 4; i++) acc[mt][nt][i] = 0.f;
            }
        }
        // issue WB chunk 0
        {
#pragma unroll
            for (int i = 0; i < 5; i++) {
                int lin = tid + TB * i;
                if (lin < 1152) cpasync16(sb + (OF_W + 0) * 4 + lin * 16, (const uint4*)gWB + lin);
            }
            CP_COMMIT();
        }
        CP_WAIT0();
        __syncthreads();   // H + WB0 visible

        // ================= layer B =================
        for (int c = 0; c < NCH_B; c++) {
            if (c == 0) {
                const uint4* gsrc = (const uint4*)(gWB + WTILE);
#pragma unroll
                for (int i = 0; i < 5; i++) {
                    int lin = tid + TB * i;
                    if (lin < 1152) cpasync16(sb + (OF_W + 4608) * 4 + lin * 16, gsrc + lin);
                }
                CP_COMMIT();
            } else {
                CP_WAIT0();
                __syncthreads();
            }
            const uint32_t* W32 = sW + c * 4608;
#pragma unroll
            for (int kk = 0; kk < 4; kk++) {
                const int kb = kk * 8;
                const int ka = c * 32 + kk * 8;
                uint32_t bf0[4], bf1[4];
#pragma unroll
                for (int nt = 0; nt < 4; nt++) {
                    int ncol = wn * 32 + nt * 8 + grp;
                    bf0[nt] = W32[ncol * WSTR2 + kb + qq];
                    bf1[nt] = W32[ncol * WSTR2 + kb + 4 + qq];
                }
#pragma unroll
                for (int mt = 0; mt < 4; mt++) {
                    int r = wm * 64 + mt * 16 + grp;
                    uint32_t a0 = U[r * HSTR2 + ka + qq];
                    uint32_t a1 = U[(r + 8) * HSTR2 + ka + qq];
                    uint32_t a2 = U[r * HSTR2 + ka + 4 + qq];
                    uint32_t a3 = U[(r + 8) * HSTR2 + ka + 4 + qq];
#pragma unroll
                    for (int nt = 0; nt < 4; nt++)
                        mma16(acc[mt][nt], a0, a1, a2, a3, bf0[nt], bf1[nt]);
                }
            }
        }
        __syncthreads();
        if (tid < 128) sRed[tid] = 0.f;
        __syncthreads();

        // ---- gate dot ----
#pragma unroll
        for (int mt = 0; mt < 4; mt++) {
            int r = wm * 64 + mt * 16 + grp;
            float d0 = 0.f, d1 = 0.f;
#pragma unroll
            for (int nt = 0; nt < 4; nt++) {
                int cc = wn * 32 + nt * 8 + 2 * qq;
                float w0 = sWg[cc], w1 = sWg[cc + 1];
                d0 += lrelu(acc[mt][nt][0] + sBlb[cc]) * w0
                    + lrelu(acc[mt][nt][1] + sBlb[cc + 1]) * w1;
                d1 += lrelu(acc[mt][nt][2] + sBlb[cc]) * w0
                    + lrelu(acc[mt][nt][3] + sBlb[cc + 1]) * w1;
            }
            d0 += __shfl_xor_sync(0xffffffffu, d0, 1);
            d0 += __shfl_xor_sync(0xffffffffu, d0, 2);
            d1 += __shfl_xor_sync(0xffffffffu, d1, 1);
            d1 += __shfl_xor_sync(0xffffffffu, d1, 2);
            if (qq == 0) {
                atomicAdd(&sRed[r], d0);
                atomicAdd(&sRed[r + 8], d1);
            }
        }
        __syncthreads();

        // ---- gate apply; p0: park g1 in regs; p1: combine + scatter ----
#pragma unroll
        for (int mt = 0; mt < 4; mt++) {
            int r = wm * 64 + mt * 16 + grp;
            float sig0 = 1.f / (1.f + __expf(-(sRed[r] + bg)));
            float sig1 = 1.f / (1.f + __expf(-(sRed[r + 8] + bg)));
            if (p == 0) {
#pragma unroll
                for (int nt = 0; nt < 4; nt++) {
                    int cc = wn * 32 + nt * 8 + 2 * qq;
                    int gi = (mt * 4 + nt) * 2;
                    g1h[gi]     = h2bits(sig0 * lrelu(acc[mt][nt][0] + sBlb[cc]),
                                         sig0 * lrelu(acc[mt][nt][1] + sBlb[cc + 1]));
                    g1h[gi + 1] = h2bits(sig1 * lrelu(acc[mt][nt][2] + sBlb[cc]),
                                         sig1 * lrelu(acc[mt][nt][3] + sBlb[cc + 1]));
                }
            } else {
                bool v0 = sE[r] >= 0, v1 = sE[r + 8] >= 0;
                float* d0p = out + ((size_t)b * NNODE + sI2[r]) * DOUT;
                float* d1p = out + ((size_t)b * NNODE + sI2[r + 8]) * DOUT;
#pragma unroll
                for (int nt = 0; nt < 4; nt++) {
                    int cc = wn * 32 + nt * 8 + 2 * qq;
                    int gi = (mt * 4 + nt) * 2;
                    float2 ga = h2f2(g1h[gi]);
                    float2 gb = h2f2(g1h[gi + 1]);
                    if (v0) {
                        atomicAdd(d0p + cc,     sig0 * lrelu(acc[mt][nt][0] + sBlb[cc])     + ga.x);
                        atomicAdd(d0p + cc + 1, sig0 * lrelu(acc[mt][nt][1] + sBlb[cc + 1]) + ga.y);
                    }
                    if (v1) {
                        atomicAdd(d1p + cc,     sig1 * lrelu(acc[mt][nt][2] + sBlb[cc])     + gb.x);
                        atomicAdd(d1p + cc + 1, sig1 * lrelu(acc[mt][nt][3] + sBlb[cc + 1]) + gb.y);
                    }
                }
            }
        }
    } // p
}

// ---------------- launcher ----------------
extern "C" void kernel_launch(void* const* d_in, const int* in_sizes, int n_in,
                              void* d_out, int out_size) {
    (void)in_sizes; (void)n_in;
    const float* sites = (const float*)d_in[0];
    const float* bonds = (const float*)d_in[1];
    const int*   idx1  = (const int*)d_in[2];
    const int*   idx2  = (const int*)d_in[3];
    const int*   uc    = (const int*)d_in[4];
    const float* W1a = (const float*)d_in[5];
    const float* b1a = (const float*)d_in[6];
    const float* W1b = (const float*)d_in[7];
    const float* b1b = (const float*)d_in[8];
    const float* W2a = (const float*)d_in[9];
    const float* b2a = (const float*)d_in[10];
    const float* W2b = (const float*)d_in[11];
    const float* b2b = (const float*)d_in[12];
    const float* Wa1 = (const float*)d_in[13];
    const float* ba1 = (const float*)d_in[14];
    const float* Wa2 = (const float*)d_in[15];
    const float* ba2 = (const float*)d_in[16];
    float* out = (float*)d_out;

    cudaFuncSetAttribute(k_fused, cudaFuncAttributeMaxDynamicSharedMemorySize, SMEM_BYTES);

    k_init<<<(out_size + TB - 1) / TB, TB>>>(out, out_size);
    k_hist<<<NEDGE / TB, TB>>>(uc);
    k_prefix<<<1, 1>>>();
    k_order<<<NEDGE / TB, TB>>>(uc);
    {
        const int total = 2 * NT * (NCH_A + NCH_B) * 4096;
        k_prepw<<<(total + TB - 1) / TB, TB>>>(W1a, W2a, W1b, W2b);
    }
    dim3 grid(MAX_TILES, BATCH);
    k_fused<<<grid, TB, SMEM_BYTES>>>(sites, bonds, idx1, idx2,
                                      b1a, b1b, b2a, b2b,
                                      Wa1, ba1, Wa2, ba2, out);
}

// round 5
// speedup vs baseline: 3.9216x; 1.0924x over previous
#include <cuda_runtime.h>
#include <cuda_fp16.h>
#include <cstdint>

// ---------------- problem constants ----------------
#define BATCH 4
#define NNODE 4096
#define NEDGE 65536
#define DIN   128
#define DBOND 64
#define DOUT  128
#define NT    4
#define DCAT  320

#define TM    64                   // edges per tile
#define TB    256
#define NCH_A 5                    // k-chunks of 64 over DCAT=320
#define NCH_B 2                    // over DOUT=128
#define WSTR2 36                   // W tile row stride (half2 units)
#define WTILE (128*WSTR2)          // 4608 u32 per chunk tile
#define ASTR2 36
#define HSTR2 68
#define NTILES (NEDGE/TM + NT)     // 1028
#define NHB   256                  // histogram blocks (256 edges each)

// ---------------- device scratch ----------------
__device__ int g_poff[NT + 1];
__device__ __align__(16) int g_bcnt[NHB * NT];
__device__ __align__(16) int g_bbase[NHB * NT];
__device__ __align__(16) int g_order[NEDGE + NT * TM];
__device__ uint32_t g_WAh[2 * NT * NCH_A * WTILE];
__device__ uint32_t g_WBh[2 * NT * NCH_B * WTILE];

// ---------------- helpers ----------------
__device__ __forceinline__ float lrelu(float x) { return x > 0.f ? x : 0.01f * x; }
__device__ __forceinline__ uint32_t h2bits(float a, float b) {
    __half2 h = __floats2half2_rn(a, b);
    return *reinterpret_cast<uint32_t*>(&h);
}
__device__ __forceinline__ float2 h2f2(uint32_t u) {
    __half2 h = *reinterpret_cast<__half2*>(&u);
    return __half22float2(h);
}
__device__ __forceinline__ uint32_t smem_u32(const void* p) {
    uint32_t a;
    asm("{ .reg .u64 t; cvta.to.shared.u64 t, %1; cvt.u32.u64 %0, t; }" : "=r"(a) : "l"(p));
    return a;
}
__device__ __forceinline__ void cpasync16(uint32_t saddr, const void* g) {
    asm volatile("cp.async.ca.shared.global [%0], [%1], 16;" :: "r"(saddr), "l"(g));
}
#define CP_COMMIT() asm volatile("cp.async.commit_group;" ::: "memory")
__device__ __forceinline__ void cp_wait_n(int n) {
    switch (n) {
        case 0: asm volatile("cp.async.wait_group 0;" ::: "memory"); break;
        case 1: asm volatile("cp.async.wait_group 1;" ::: "memory"); break;
        case 2: asm volatile("cp.async.wait_group 2;" ::: "memory"); break;
        case 3: asm volatile("cp.async.wait_group 3;" ::: "memory"); break;
        case 4: asm volatile("cp.async.wait_group 4;" ::: "memory"); break;
        case 5: asm volatile("cp.async.wait_group 5;" ::: "memory"); break;
        default: asm volatile("cp.async.wait_group 6;" ::: "memory"); break;
    }
}

__device__ __forceinline__ void mma16(float* d, uint32_t a0, uint32_t a1, uint32_t a2, uint32_t a3,
                                      uint32_t b0, uint32_t b1) {
    asm volatile(
        "mma.sync.aligned.m16n8k16.row.col.f32.f16.f16.f32 "
        "{%0,%1,%2,%3},{%4,%5,%6,%7},{%8,%9},{%0,%1,%2,%3};"
        : "+f"(d[0]), "+f"(d[1]), "+f"(d[2]), "+f"(d[3])
        : "r"(a0), "r"(a1), "r"(a2), "r"(a3), "r"(b0), "r"(b1));
}

// ---------------- prep kernels ----------------
__global__ void k_zero(float* __restrict__ out, int n_out) {
    int i = blockIdx.x * blockDim.x + threadIdx.x;
    int n4 = n_out >> 2;
    if (i < n4) ((float4*)out)[i] = make_float4(0.f, 0.f, 0.f, 0.f);
    if (i < (NEDGE + NT * TM) / 4) ((int4*)g_order)[i] = make_int4(-1, -1, -1, -1);
}

__global__ void k_hist(const int* __restrict__ uc) {
    __shared__ int cnt[NT];
    int tid = threadIdx.x;
    if (tid < NT) cnt[tid] = 0;
    __syncthreads();
    atomicAdd(&cnt[uc[blockIdx.x * 256 + tid]], 1);
    __syncthreads();
    if (tid < NT) g_bcnt[blockIdx.x * NT + tid] = cnt[tid];
}

__global__ void k_scan() {
    __shared__ int wsum[8][NT];
    __shared__ int tot[NT];
    int tid = threadIdx.x, lane = tid & 31, w = tid >> 5;
    int4 v = ((const int4*)g_bcnt)[tid];
    int4 orig = v;
#pragma unroll
    for (int d = 1; d < 32; d <<= 1) {
        int x = __shfl_up_sync(~0u, v.x, d), y = __shfl_up_sync(~0u, v.y, d);
        int z = __shfl_up_sync(~0u, v.z, d), q = __shfl_up_sync(~0u, v.w, d);
        if (lane >= d) { v.x += x; v.y += y; v.z += z; v.w += q; }
    }
    if (lane == 31) { wsum[w][0] = v.x; wsum[w][1] = v.y; wsum[w][2] = v.z; wsum[w][3] = v.w; }
    __syncthreads();
    if (tid == 0) {
        int a0 = 0, a1 = 0, a2 = 0, a3 = 0;
        for (int i = 0; i < 8; i++) {
            int t0 = wsum[i][0], t1 = wsum[i][1], t2 = wsum[i][2], t3 = wsum[i][3];
            wsum[i][0] = a0; wsum[i][1] = a1; wsum[i][2] = a2; wsum[i][3] = a3;
            a0 += t0; a1 += t1; a2 += t2; a3 += t3;
        }
        tot[0] = a0; tot[1] = a1; tot[2] = a2; tot[3] = a3;
    }
    __syncthreads();
    // exclusive scan values
    int e0 = v.x + wsum[w][0] - orig.x;
    int e1 = v.y + wsum[w][1] - orig.y;
    int e2 = v.z + wsum[w][2] - orig.z;
    int e3 = v.w + wsum[w][3] - orig.w;
    int p0 = 0;
    int p1 = p0 + ((tot[0] + TM - 1) / TM) * TM;
    int p2 = p1 + ((tot[1] + TM - 1) / TM) * TM;
    int p3 = p2 + ((tot[2] + TM - 1) / TM) * TM;
    int p4 = p3 + ((tot[3] + TM - 1) / TM) * TM;
    int4 bb; bb.x = p0 + e0; bb.y = p1 + e1; bb.z = p2 + e2; bb.w = p3 + e3;
    ((int4*)g_bbase)[tid] = bb;
    if (tid == 0) {
        g_poff[0] = p0; g_poff[1] = p1; g_poff[2] = p2; g_poff[3] = p3; g_poff[4] = p4;
    }
}

__global__ void k_scatter(const int* __restrict__ uc) {
    __shared__ int base[NT];
    __shared__ int cur[NT];
    int tid = threadIdx.x;
    if (tid < NT) { base[tid] = g_bbase[blockIdx.x * NT + tid]; cur[tid] = 0; }
    __syncthreads();
    int e = blockIdx.x * 256 + tid;
    int t = uc[e];
    int pos = atomicAdd(&cur[t], 1);
    g_order[base[t] + pos] = e;
}

// coalesced weight transpose+fp16 pack via smem staging; 56 blocks
__global__ void k_prepw(const float* __restrict__ W1a, const float* __restrict__ W2a,
                        const float* __restrict__ W1b, const float* __restrict__ W2b) {
    __shared__ float smw[64 * 129];
    int blk = blockIdx.x;
    bool isA = blk < 2 * NT * NCH_A;      // 40
    int c, pt;
    if (isA) { c = blk % NCH_A; pt = blk / NCH_A; }
    else     { int j = blk - 2 * NT * NCH_A; c = j % NCH_B; pt = j / NCH_B; }
    int t = pt & 3, p = pt >> 2;
    int ld = isA ? DCAT : DOUT;
    const float* W = isA ? (p ? W2a : W1a) : (p ? W2b : W1b);
    int tid = threadIdx.x;
#pragma unroll
    for (int i = 0; i < 32; i++) {
        int lin = tid + 256 * i;            // 8192 = 64k x 128n
        int k = lin >> 7, n = lin & 127;
        smw[k * 129 + n] = W[((size_t)t * ld + c * 64 + k) * DOUT + n];
    }
    __syncthreads();
    uint32_t* dst = isA ? (g_WAh + (size_t)(pt * NCH_A + c) * WTILE)
                        : (g_WBh + (size_t)(pt * NCH_B + c) * WTILE);
#pragma unroll
    for (int i = 0; i < 16; i++) {
        int lin = tid + 256 * i;            // 4096 = 128n x 32k2
        int n = lin >> 5, k2 = lin & 31;
        dst[n * WSTR2 + k2] = h2bits(smw[(2 * k2) * 129 + n], smw[(2 * k2 + 1) * 129 + n]);
    }
}

// ---------------- fused kernel smem layout (u32) ----------------
#define OFW    0                      // 7 x 4608 = 32256
#define OFA    32256                  // 2 x 2304 A staging; H alias (64 x 68)
#define OFRED  36864                  // 64
#define OFBIAS 36928                  // 6 x 128
#define OFE    37696
#define OFI1   37760
#define OFI2   37824
#define SMEM_U32 37888
#define SMEM_BYTES (SMEM_U32 * 4)

__device__ __forceinline__ void copy_chunk(uint32_t sdst, const uint32_t* __restrict__ g, int tid) {
    const uint4* gs = (const uint4*)g;
#pragma unroll
    for (int i = 0; i < 5; i++) {
        int lin = tid + TB * i;
        if (lin < 1152) cpasync16(sdst + lin * 16, gs + lin);
    }
    CP_COMMIT();
}

__device__ __forceinline__ void gatherChunk(float4* pA, const float* __restrict__ sites,
                                            const float* __restrict__ bonds, int b,
                                            const int* sE, const int* sI1, const int* sI2,
                                            int c, int tid) {
#pragma unroll
    for (int i = 0; i < 4; i++) {
        int lin = tid + TB * i;
        int row = lin >> 4, col = (lin & 15) << 2;
        const float* src;
        if (c < 2)      src = sites + ((size_t)b * NNODE + sI1[row]) * DIN + c * 64 + col;
        else if (c < 4) src = sites + ((size_t)b * NNODE + sI2[row]) * DIN + (c - 2) * 64 + col;
        else { int e = sE[row]; if (e < 0) e = 0;
               src = bonds + ((size_t)b * NEDGE + e) * DBOND + col; }
        pA[i] = *(const float4*)src;
    }
}

__device__ __forceinline__ void mmaChunk(const uint32_t* __restrict__ A32, int astr,
                                         const uint32_t* __restrict__ W32,
                                         float acc[2][4][4], int wm, int wn, int grp, int qq) {
#pragma unroll
    for (int kk = 0; kk < 4; kk++) {
        const int kb = kk * 8;
        uint32_t bf0[4], bf1[4];
#pragma unroll
        for (int nt = 0; nt < 4; nt++) {
            int ncol = wn * 32 + nt * 8 + grp;
            bf0[nt] = W32[ncol * WSTR2 + kb + qq];
            bf1[nt] = W32[ncol * WSTR2 + kb + 4 + qq];
        }
#pragma unroll
        for (int mt = 0; mt < 2; mt++) {
            int r = wm * 32 + mt * 16 + grp;
            uint32_t a0 = A32[r * astr + kb + qq];
            uint32_t a1 = A32[(r + 8) * astr + kb + qq];
            uint32_t a2 = A32[r * astr + kb + 4 + qq];
            uint32_t a3 = A32[(r + 8) * astr + kb + 4 + qq];
#pragma unroll
            for (int nt = 0; nt < 4; nt++)
                mma16(acc[mt][nt], a0, a1, a2, a3, bf0[nt], bf1[nt]);
        }
    }
}

__global__ void __launch_bounds__(TB) k_fused(
    const float* __restrict__ sites, const float* __restrict__ bonds,
    const int* __restrict__ idx1, const int* __restrict__ idx2,
    const float* __restrict__ b1a, const float* __restrict__ b1b,
    const float* __restrict__ b2a, const float* __restrict__ b2b,
    const float* __restrict__ Wa1, const float* __restrict__ ba1,
    const float* __restrict__ Wa2, const float* __restrict__ ba2,
    float* __restrict__ out)
{
    extern __shared__ uint32_t sm[];
    uint32_t* sA0 = sm + OFA;
    uint32_t* sA1 = sm + OFA + TM * ASTR2;
    uint32_t* sH  = sm + OFA;                 // alias (layer A done before H write)
    float* sRed  = (float*)(sm + OFRED);
    float* sBias = (float*)(sm + OFBIAS);
    int* sE  = (int*)(sm + OFE);
    int* sI1 = (int*)(sm + OFI1);
    int* sI2 = (int*)(sm + OFI2);
    const uint32_t sb = smem_u32(sm);

    const int tile  = blockIdx.x;
    const int start = tile * TM;
    if (start >= g_poff[NT]) return;
    int t = 0;
#pragma unroll
    for (int i = 1; i < NT; i++) if (start >= g_poff[i]) t = i;

    const int tid  = threadIdx.x;
    const int lane = tid & 31;
    const int wid  = tid >> 5;
    const int wm   = wid & 1;
    const int wn   = wid >> 1;
    const int grp  = lane >> 2;
    const int qq   = lane & 3;

    if (tid < TM) {
        int e = g_order[start + tid];
        sE[tid] = e;
        int es = e < 0 ? 0 : e;
        sI1[tid] = idx1[es];
        sI2[tid] = idx2[es];
    }
    if (tid < 128) {
        sBias[0 * 128 + tid] = b1a[t * DOUT + tid];
        sBias[1 * 128 + tid] = b1b[t * DOUT + tid];
        sBias[2 * 128 + tid] = Wa1[tid];
        sBias[3 * 128 + tid] = b2a[t * DOUT + tid];
        sBias[4 * 128 + tid] = b2b[t * DOUT + tid];
        sBias[5 * 128 + tid] = Wa2[tid];
    }
    __syncthreads();

    uint32_t g1h[64];
    float4 pA[4];

    for (int p = 0; p < 2; p++) {
        const float* sBla = sBias + (p * 3 + 0) * 128;
        const float* sBlb = sBias + (p * 3 + 1) * 128;
        const float* sWg  = sBias + (p * 3 + 2) * 128;
        const float bg = p ? ba2[0] : ba1[0];
        const uint32_t* gWA = g_WAh + (size_t)((p * NT + t) * NCH_A) * WTILE;
        const uint32_t* gWB = g_WBh + (size_t)((p * NT + t) * NCH_B) * WTILE;

        __syncthreads();   // previous phase done reading W buffers
#pragma unroll
        for (int ci = 0; ci < NCH_A; ci++)
            copy_chunk(sb + (OFW + ci * 4608) * 4, gWA + (size_t)ci * WTILE, tid);
#pragma unroll
        for (int ci = 0; ci < NCH_B; ci++)
            copy_chunk(sb + (OFW + (NCH_A + ci) * 4608) * 4, gWB + (size_t)ci * WTILE, tid);

        if (p == 0) gatherChunk(pA, sites, bonds, 0, sE, sI1, sI2, 0, tid);

#pragma unroll
        for (int bb = 0; bb < BATCH; bb++) {
            float acc[2][4][4];
#pragma unroll
            for (int mt = 0; mt < 2; mt++)
#pragma unroll
                for (int nt = 0; nt < 4; nt++)
#pragma unroll
                    for (int i = 0; i < 4; i++) acc[mt][nt][i] = 0.f;

            // ---------------- layer A ----------------
#pragma unroll
            for (int c = 0; c < NCH_A; c++) {
                uint32_t* Ab = (c & 1) ? sA1 : sA0;
#pragma unroll
                for (int i = 0; i < 4; i++) {
                    int lin = tid + TB * i;
                    int row = lin >> 4, j = (lin & 15) << 1;
                    uint2 v;
                    v.x = h2bits(pA[i].x, pA[i].y);
                    v.y = h2bits(pA[i].z, pA[i].w);
                    *(uint2*)(Ab + row * ASTR2 + j) = v;
                }
                if (bb == 0) cp_wait_n(6 - c);
                __syncthreads();
                if (c + 1 < NCH_A)
                    gatherChunk(pA, sites, bonds, bb, sE, sI1, sI2, c + 1, tid);
                mmaChunk(Ab, ASTR2, sm + OFW + c * 4608, acc, wm, wn, grp, qq);
            }
            __syncthreads();   // all layer-A smem reads done

            // ---- epilogue A: H = fp16(lrelu(acc + bla)) ----
#pragma unroll
            for (int mt = 0; mt < 2; mt++) {
                int r = wm * 32 + mt * 16 + grp;
#pragma unroll
                for (int nt = 0; nt < 4; nt++) {
                    int cc = wn * 32 + nt * 8 + 2 * qq;
                    int col2 = wn * 16 + nt * 4 + qq;
                    sH[r * HSTR2 + col2] =
                        h2bits(lrelu(acc[mt][nt][0] + sBla[cc]), lrelu(acc[mt][nt][1] + sBla[cc + 1]));
                    sH[(r + 8) * HSTR2 + col2] =
                        h2bits(lrelu(acc[mt][nt][2] + sBla[cc]), lrelu(acc[mt][nt][3] + sBla[cc + 1]));
#pragma unroll
                    for (int i = 0; i < 4; i++) acc[mt][nt][i] = 0.f;
                }
            }
            // prefetch next (phase,batch) chunk0 while layer B runs
            if (!(p == 1 && bb == 3))
                gatherChunk(pA, sites, bonds, (bb + 1) & 3, sE, sI1, sI2, 0, tid);
            if (bb == 0) cp_wait_n(0);     // WB chunks resident
            __syncthreads();               // H visible (+ WB for bb==0)

            // ---------------- layer B ----------------
#pragma unroll
            for (int c = 0; c < NCH_B; c++)
                mmaChunk(sH + c * 32, HSTR2, sm + OFW + (NCH_A + c) * 4608, acc, wm, wn, grp, qq);

            __syncthreads();
            if (tid < TM) sRed[tid] = 0.f;
            __syncthreads();

            // ---- gate dot ----
#pragma unroll
            for (int mt = 0; mt < 2; mt++) {
                int r = wm * 32 + mt * 16 + grp;
                float d0 = 0.f, d1 = 0.f;
#pragma unroll
                for (int nt = 0; nt < 4; nt++) {
                    int cc = wn * 32 + nt * 8 + 2 * qq;
                    float w0 = sWg[cc], w1 = sWg[cc + 1];
                    d0 += lrelu(acc[mt][nt][0] + sBlb[cc]) * w0
                        + lrelu(acc[mt][nt][1] + sBlb[cc + 1]) * w1;
                    d1 += lrelu(acc[mt][nt][2] + sBlb[cc]) * w0
                        + lrelu(acc[mt][nt][3] + sBlb[cc + 1]) * w1;
                }
                d0 += __shfl_xor_sync(0xffffffffu, d0, 1);
                d0 += __shfl_xor_sync(0xffffffffu, d0, 2);
                d1 += __shfl_xor_sync(0xffffffffu, d1, 1);
                d1 += __shfl_xor_sync(0xffffffffu, d1, 2);
                if (qq == 0) {
                    atomicAdd(&sRed[r], d0);
                    atomicAdd(&sRed[r + 8], d1);
                }
            }
            __syncthreads();

            // ---- gate apply: p0 park g1 in regs; p1 combine + scatter ----
#pragma unroll
            for (int mt = 0; mt < 2; mt++) {
                int r = wm * 32 + mt * 16 + grp;
                float sig0 = 1.f / (1.f + __expf(-(sRed[r] + bg)));
                float sig1 = 1.f / (1.f + __expf(-(sRed[r + 8] + bg)));
                if (p == 0) {
#pragma unroll
                    for (int nt = 0; nt < 4; nt++) {
                        int cc = wn * 32 + nt * 8 + 2 * qq;
                        int gi = bb * 16 + (mt * 4 + nt) * 2;
                        g1h[gi]     = h2bits(sig0 * lrelu(acc[mt][nt][0] + sBlb[cc]),
                                             sig0 * lrelu(acc[mt][nt][1] + sBlb[cc + 1]));
                        g1h[gi + 1] = h2bits(sig1 * lrelu(acc[mt][nt][2] + sBlb[cc]),
                                             sig1 * lrelu(acc[mt][nt][3] + sBlb[cc + 1]));
                    }
                } else {
                    bool v0 = sE[r] >= 0, v1 = sE[r + 8] >= 0;
                    float* d0p = out + ((size_t)bb * NNODE + sI2[r]) * DOUT;
                    float* d1p = out + ((size_t)bb * NNODE + sI2[r + 8]) * DOUT;
#pragma unroll
                    for (int nt = 0; nt < 4; nt++) {
                        int cc = wn * 32 + nt * 8 + 2 * qq;
                        int gi = bb * 16 + (mt * 4 + nt) * 2;
                        float2 ga = h2f2(g1h[gi]);
                        float2 gb = h2f2(g1h[gi + 1]);
                        if (v0) {
                            atomicAdd(d0p + cc,     sig0 * lrelu(acc[mt][nt][0] + sBlb[cc])     + ga.x);
                            atomicAdd(d0p + cc + 1, sig0 * lrelu(acc[mt][nt][1] + sBlb[cc + 1]) + ga.y);
                        }
                        if (v1) {
                            atomicAdd(d1p + cc,     sig1 * lrelu(acc[mt][nt][2] + sBlb[cc])     + gb.x);
                            atomicAdd(d1p + cc + 1, sig1 * lrelu(acc[mt][nt][3] + sBlb[cc + 1]) + gb.y);
                        }
                    }
                }
            }
        } // bb
    } // p
}

// ---------------- launcher ----------------
extern "C" void kernel_launch(void* const* d_in, const int* in_sizes, int n_in,
                              void* d_out, int out_size) {
    (void)in_sizes; (void)n_in;
    const float* sites = (const float*)d_in[0];
    const float* bonds = (const float*)d_in[1];
    const int*   idx1  = (const int*)d_in[2];
    const int*   idx2  = (const int*)d_in[3];
    const int*   uc    = (const int*)d_in[4];
    const float* W1a = (const float*)d_in[5];
    const float* b1a = (const float*)d_in[6];
    const float* W1b = (const float*)d_in[7];
    const float* b1b = (const float*)d_in[8];
    const float* W2a = (const float*)d_in[9];
    const float* b2a = (const float*)d_in[10];
    const float* W2b = (const float*)d_in[11];
    const float* b2b = (const float*)d_in[12];
    const float* Wa1 = (const float*)d_in[13];
    const float* ba1 = (const float*)d_in[14];
    const float* Wa2 = (const float*)d_in[15];
    const float* ba2 = (const float*)d_in[16];
    float* out = (float*)d_out;

    cudaFuncSetAttribute(k_fused, cudaFuncAttributeMaxDynamicSharedMemorySize, SMEM_BYTES);

    k_zero<<<(out_size / 4 + TB - 1) / TB, TB>>>(out, out_size);
    k_hist<<<NHB, 256>>>(uc);
    k_scan<<<1, 256>>>();
    k_scatter<<<NHB, 256>>>(uc);
    k_prepw<<<2 * NT * (NCH_A + NCH_B), 256>>>(W1a, W2a, W1b, W2b);
    k_fused<<<NTILES, TB, SMEM_BYTES>>>(sites, bonds, idx1, idx2,
                                        b1a, b1b, b2a, b2b,
                                        Wa1, ba1, Wa2, ba2, out);
}

// round 6
// speedup vs baseline: 4.0439x; 1.0312x over previous
#include <cuda_runtime.h>
#include <cuda_fp16.h>
#include <cstdint>

// ---------------- problem constants ----------------
#define BATCH 4
#define NNODE 4096
#define NEDGE 65536
#define DIN   128
#define DBOND 64
#define DOUT  128
#define NT    4
#define DCAT  320

#define TM    64                   // edges per tile
#define TB    256
#define NCH_A 5                    // k-chunks of 64 over DCAT=320
#define NCH_B 2                    // over DOUT=128
#define WSTR2 36                   // W tile row stride (half2 units)
#define WTILE (128*WSTR2)          // 4608 u32 per chunk tile
#define ASTR2 36
#define HSTR2 68
#define NTILES (NEDGE/TM + NT)     // 1028
#define NHB   256                  // histogram blocks (256 edges each)

// k_prep grid split
#define PB_ZERO 2048               // out zero blocks (2048*256*4 floats = 2M)
#define PB_HIST NHB
#define PB_PREPW (2*NT*(NCH_A+NCH_B))   // 56

// ---------------- device scratch ----------------
__device__ int g_poff[NT + 1];
__device__ __align__(16) int g_bcnt[NHB * NT];
__device__ __align__(16) int g_bbase[NHB * NT];
__device__ __align__(16) int g_order[NEDGE + NT * TM];
__device__ uint32_t g_WAh[2 * NT * NCH_A * WTILE];
__device__ uint32_t g_WBh[2 * NT * NCH_B * WTILE];

// ---------------- helpers ----------------
__device__ __forceinline__ float lrelu(float x) { return x > 0.f ? x : 0.01f * x; }
__device__ __forceinline__ uint32_t h2bits(float a, float b) {
    __half2 h = __floats2half2_rn(a, b);
    return *reinterpret_cast<uint32_t*>(&h);
}
__device__ __forceinline__ float2 h2f2(uint32_t u) {
    __half2 h = *reinterpret_cast<__half2*>(&u);
    return __half22float2(h);
}
__device__ __forceinline__ uint32_t smem_u32(const void* p) {
    uint32_t a;
    asm("{ .reg .u64 t; cvta.to.shared.u64 t, %1; cvt.u32.u64 %0, t; }" : "=r"(a) : "l"(p));
    return a;
}
__device__ __forceinline__ void cpasync16(uint32_t saddr, const void* g) {
    asm volatile("cp.async.ca.shared.global [%0], [%1], 16;" :: "r"(saddr), "l"(g));
}
#define CP_COMMIT() asm volatile("cp.async.commit_group;" ::: "memory")
__device__ __forceinline__ void cp_wait_n(int n) {
    switch (n) {
        case 0: asm volatile("cp.async.wait_group 0;" ::: "memory"); break;
        case 1: asm volatile("cp.async.wait_group 1;" ::: "memory"); break;
        case 2: asm volatile("cp.async.wait_group 2;" ::: "memory"); break;
        case 3: asm volatile("cp.async.wait_group 3;" ::: "memory"); break;
        case 4: asm volatile("cp.async.wait_group 4;" ::: "memory"); break;
        case 5: asm volatile("cp.async.wait_group 5;" ::: "memory"); break;
        default: asm volatile("cp.async.wait_group 6;" ::: "memory"); break;
    }
}
__device__ __forceinline__ void red2(float* addr, float a, float b) {
    asm volatile("red.global.add.v2.f32 [%0], {%1, %2};" :: "l"(addr), "f"(a), "f"(b) : "memory");
}

__device__ __forceinline__ void mma16(float* d, uint32_t a0, uint32_t a1, uint32_t a2, uint32_t a3,
                                      uint32_t b0, uint32_t b1) {
    asm volatile(
        "mma.sync.aligned.m16n8k16.row.col.f32.f16.f16.f32 "
        "{%0,%1,%2,%3},{%4,%5,%6,%7},{%8,%9},{%0,%1,%2,%3};"
        : "+f"(d[0]), "+f"(d[1]), "+f"(d[2]), "+f"(d[3])
        : "r"(a0), "r"(a1), "r"(a2), "r"(a3), "r"(b0), "r"(b1));
}

// ---------------- prep kernel (merged: zero | hist | prepw) ----------------
__global__ void k_prep(float* __restrict__ out, int n_out, const int* __restrict__ uc,
                       const float* __restrict__ W1a, const float* __restrict__ W2a,
                       const float* __restrict__ W1b, const float* __restrict__ W2b) {
    __shared__ int cnt[NT];
    __shared__ float smw[64 * 129];
    const int blk = blockIdx.x;
    const int tid = threadIdx.x;

    if (blk < PB_ZERO) {
        int i = blk * 256 + tid;
        if (i < (n_out >> 2)) ((float4*)out)[i] = make_float4(0.f, 0.f, 0.f, 0.f);
        if (i < (NEDGE + NT * TM) / 4) ((int4*)g_order)[i] = make_int4(-1, -1, -1, -1);
        return;
    }
    if (blk < PB_ZERO + PB_HIST) {
        int hb = blk - PB_ZERO;
        if (tid < NT) cnt[tid] = 0;
        __syncthreads();
        atomicAdd(&cnt[uc[hb * 256 + tid]], 1);
        __syncthreads();
        if (tid < NT) g_bcnt[hb * NT + tid] = cnt[tid];
        return;
    }
    // ---- weight transpose + fp16 pack ----
    int wb = blk - PB_ZERO - PB_HIST;
    bool isA = wb < 2 * NT * NCH_A;
    int c, pt;
    if (isA) { c = wb % NCH_A; pt = wb / NCH_A; }
    else     { int j = wb - 2 * NT * NCH_A; c = j % NCH_B; pt = j / NCH_B; }
    int t = pt & 3, p = pt >> 2;
    int ld = isA ? DCAT : DOUT;
    const float* W = isA ? (p ? W2a : W1a) : (p ? W2b : W1b);
#pragma unroll
    for (int i = 0; i < 32; i++) {
        int lin = tid + 256 * i;
        int k = lin >> 7, n = lin & 127;
        smw[k * 129 + n] = W[((size_t)t * ld + c * 64 + k) * DOUT + n];
    }
    __syncthreads();
    uint32_t* dst = isA ? (g_WAh + (size_t)(pt * NCH_A + c) * WTILE)
                        : (g_WBh + (size_t)(pt * NCH_B + c) * WTILE);
#pragma unroll
    for (int i = 0; i < 16; i++) {
        int lin = tid + 256 * i;
        int n = lin >> 5, k2 = lin & 31;
        dst[n * WSTR2 + k2] = h2bits(smw[(2 * k2) * 129 + n], smw[(2 * k2 + 1) * 129 + n]);
    }
}

__global__ void k_scan() {
    __shared__ int wsum[8][NT];
    __shared__ int tot[NT];
    int tid = threadIdx.x, lane = tid & 31, w = tid >> 5;
    int4 v = ((const int4*)g_bcnt)[tid];
    int4 orig = v;
#pragma unroll
    for (int d = 1; d < 32; d <<= 1) {
        int x = __shfl_up_sync(~0u, v.x, d), y = __shfl_up_sync(~0u, v.y, d);
        int z = __shfl_up_sync(~0u, v.z, d), q = __shfl_up_sync(~0u, v.w, d);
        if (lane >= d) { v.x += x; v.y += y; v.z += z; v.w += q; }
    }
    if (lane == 31) { wsum[w][0] = v.x; wsum[w][1] = v.y; wsum[w][2] = v.z; wsum[w][3] = v.w; }
    __syncthreads();
    if (tid == 0) {
        int a0 = 0, a1 = 0, a2 = 0, a3 = 0;
        for (int i = 0; i < 8; i++) {
            int t0 = wsum[i][0], t1 = wsum[i][1], t2 = wsum[i][2], t3 = wsum[i][3];
            wsum[i][0] = a0; wsum[i][1] = a1; wsum[i][2] = a2; wsum[i][3] = a3;
            a0 += t0; a1 += t1; a2 += t2; a3 += t3;
        }
        tot[0] = a0; tot[1] = a1; tot[2] = a2; tot[3] = a3;
    }
    __syncthreads();
    int e0 = v.x + wsum[w][0] - orig.x;
    int e1 = v.y + wsum[w][1] - orig.y;
    int e2 = v.z + wsum[w][2] - orig.z;
    int e3 = v.w + wsum[w][3] - orig.w;
    int p0 = 0;
    int p1 = p0 + ((tot[0] + TM - 1) / TM) * TM;
    int p2 = p1 + ((tot[1] + TM - 1) / TM) * TM;
    int p3 = p2 + ((tot[2] + TM - 1) / TM) * TM;
    int p4 = p3 + ((tot[3] + TM - 1) / TM) * TM;
    int4 bb; bb.x = p0 + e0; bb.y = p1 + e1; bb.z = p2 + e2; bb.w = p3 + e3;
    ((int4*)g_bbase)[tid] = bb;
    if (tid == 0) {
        g_poff[0] = p0; g_poff[1] = p1; g_poff[2] = p2; g_poff[3] = p3; g_poff[4] = p4;
    }
}

__global__ void k_scatter(const int* __restrict__ uc) {
    __shared__ int base[NT];
    __shared__ int cur[NT];
    int tid = threadIdx.x;
    if (tid < NT) { base[tid] = g_bbase[blockIdx.x * NT + tid]; cur[tid] = 0; }
    __syncthreads();
    int e = blockIdx.x * 256 + tid;
    int t = uc[e];
    int pos = atomicAdd(&cur[t], 1);
    g_order[base[t] + pos] = e;
}

// ---------------- fused kernel smem layout (u32) ----------------
#define OFW    0                      // 7 x 4608 = 32256
#define OFA    32256                  // 2 x 2304 A staging; H alias (64 x 68)
#define OFRED  36864                  // 64
#define OFBIAS 36928                  // 6 x 128
#define OFE    37696
#define OFI1   37760
#define OFI2   37824
#define SMEM_U32 37888
#define SMEM_BYTES (SMEM_U32 * 4)

__device__ __forceinline__ void copy_chunk(uint32_t sdst, const uint32_t* __restrict__ g, int tid) {
    const uint4* gs = (const uint4*)g;
#pragma unroll
    for (int i = 0; i < 5; i++) {
        int lin = tid + TB * i;
        if (lin < 1152) cpasync16(sdst + lin * 16, gs + lin);
    }
    CP_COMMIT();
}

__device__ __forceinline__ void gatherChunk(float4* pA, const float* __restrict__ sites,
                                            const float* __restrict__ bonds, int b,
                                            const int* sE, const int* sI1, const int* sI2,
                                            int c, int tid) {
#pragma unroll
    for (int i = 0; i < 4; i++) {
        int lin = tid + TB * i;
        int row = lin >> 4, col = (lin & 15) << 2;
        const float* src;
        if (c < 2)      src = sites + ((size_t)b * NNODE + sI1[row]) * DIN + c * 64 + col;
        else if (c < 4) src = sites + ((size_t)b * NNODE + sI2[row]) * DIN + (c - 2) * 64 + col;
        else { int e = sE[row]; if (e < 0) e = 0;
               src = bonds + ((size_t)b * NEDGE + e) * DBOND + col; }
        pA[i] = *(const float4*)src;
    }
}

__device__ __forceinline__ void mmaChunk(const uint32_t* __restrict__ A32, int astr,
                                         const uint32_t* __restrict__ W32,
                                         float acc[2][4][4], int wm, int wn, int grp, int qq) {
#pragma unroll
    for (int kk = 0; kk < 4; kk++) {
        const int kb = kk * 8;
        uint32_t bf0[4], bf1[4];
#pragma unroll
        for (int nt = 0; nt < 4; nt++) {
            int ncol = wn * 32 + nt * 8 + grp;
            bf0[nt] = W32[ncol * WSTR2 + kb + qq];
            bf1[nt] = W32[ncol * WSTR2 + kb + 4 + qq];
        }
#pragma unroll
        for (int mt = 0; mt < 2; mt++) {
            int r = wm * 32 + mt * 16 + grp;
            uint32_t a0 = A32[r * astr + kb + qq];
            uint32_t a1 = A32[(r + 8) * astr + kb + qq];
            uint32_t a2 = A32[r * astr + kb + 4 + qq];
            uint32_t a3 = A32[(r + 8) * astr + kb + 4 + qq];
#pragma unroll
            for (int nt = 0; nt < 4; nt++)
                mma16(acc[mt][nt], a0, a1, a2, a3, bf0[nt], bf1[nt]);
        }
    }
}

__global__ void __launch_bounds__(TB) k_fused(
    const float* __restrict__ sites, const float* __restrict__ bonds,
    const int* __restrict__ idx1, const int* __restrict__ idx2,
    const float* __restrict__ b1a, const float* __restrict__ b1b,
    const float* __restrict__ b2a, const float* __restrict__ b2b,
    const float* __restrict__ Wa1, const float* __restrict__ ba1,
    const float* __restrict__ Wa2, const float* __restrict__ ba2,
    float* __restrict__ out)
{
    extern __shared__ uint32_t sm[];
    uint32_t* sA0 = sm + OFA;
    uint32_t* sA1 = sm + OFA + TM * ASTR2;
    uint32_t* sH  = sm + OFA;                 // alias (layer A done before H write)
    float* sRed  = (float*)(sm + OFRED);
    float* sBias = (float*)(sm + OFBIAS);
    int* sE  = (int*)(sm + OFE);
    int* sI1 = (int*)(sm + OFI1);
    int* sI2 = (int*)(sm + OFI2);
    const uint32_t sb = smem_u32(sm);

    const int tile  = blockIdx.x;
    const int start = tile * TM;
    if (start >= g_poff[NT]) return;
    int t = 0;
#pragma unroll
    for (int i = 1; i < NT; i++) if (start >= g_poff[i]) t = i;

    const int tid  = threadIdx.x;
    const int lane = tid & 31;
    const int wid  = tid >> 5;
    const int wm   = wid & 1;
    const int wn   = wid >> 1;
    const int grp  = lane >> 2;
    const int qq   = lane & 3;

    if (tid < TM) {
        int e = g_order[start + tid];
        sE[tid] = e;
        int es = e < 0 ? 0 : e;
        sI1[tid] = idx1[es];
        sI2[tid] = idx2[es];
    }
    if (tid < 128) {
        sBias[0 * 128 + tid] = b1a[t * DOUT + tid];
        sBias[1 * 128 + tid] = b1b[t * DOUT + tid];
        sBias[2 * 128 + tid] = Wa1[tid];
        sBias[3 * 128 + tid] = b2a[t * DOUT + tid];
        sBias[4 * 128 + tid] = b2b[t * DOUT + tid];
        sBias[5 * 128 + tid] = Wa2[tid];
    }
    __syncthreads();

    uint32_t g1h[64];
    float4 pA[4];

    for (int p = 0; p < 2; p++) {
        const float* sBla = sBias + (p * 3 + 0) * 128;
        const float* sBlb = sBias + (p * 3 + 1) * 128;
        const float* sWg  = sBias + (p * 3 + 2) * 128;
        const float bg = p ? ba2[0] : ba1[0];
        const uint32_t* gWA = g_WAh + (size_t)((p * NT + t) * NCH_A) * WTILE;
        const uint32_t* gWB = g_WBh + (size_t)((p * NT + t) * NCH_B) * WTILE;

        __syncthreads();   // previous phase done reading W buffers
#pragma unroll
        for (int ci = 0; ci < NCH_A; ci++)
            copy_chunk(sb + (OFW + ci * 4608) * 4, gWA + (size_t)ci * WTILE, tid);
#pragma unroll
        for (int ci = 0; ci < NCH_B; ci++)
            copy_chunk(sb + (OFW + (NCH_A + ci) * 4608) * 4, gWB + (size_t)ci * WTILE, tid);

        if (p == 0) gatherChunk(pA, sites, bonds, 0, sE, sI1, sI2, 0, tid);

#pragma unroll
        for (int bb = 0; bb < BATCH; bb++) {
            float acc[2][4][4];
#pragma unroll
            for (int mt = 0; mt < 2; mt++)
#pragma unroll
                for (int nt = 0; nt < 4; nt++)
#pragma unroll
                    for (int i = 0; i < 4; i++) acc[mt][nt][i] = 0.f;

            // ---------------- layer A ----------------
#pragma unroll
            for (int c = 0; c < NCH_A; c++) {
                uint32_t* Ab = (c & 1) ? sA1 : sA0;
#pragma unroll
                for (int i = 0; i < 4; i++) {
                    int lin = tid + TB * i;
                    int row = lin >> 4, j = (lin & 15) << 1;
                    uint2 v;
                    v.x = h2bits(pA[i].x, pA[i].y);
                    v.y = h2bits(pA[i].z, pA[i].w);
                    *(uint2*)(Ab + row * ASTR2 + j) = v;
                }
                if (bb == 0) cp_wait_n(6 - c);
                __syncthreads();
                if (c + 1 < NCH_A)
                    gatherChunk(pA, sites, bonds, bb, sE, sI1, sI2, c + 1, tid);
                mmaChunk(Ab, ASTR2, sm + OFW + c * 4608, acc, wm, wn, grp, qq);
            }
            __syncthreads();   // all layer-A smem reads done

            // ---- epilogue A: H = fp16(lrelu(acc + bla)) ----
#pragma unroll
            for (int mt = 0; mt < 2; mt++) {
                int r = wm * 32 + mt * 16 + grp;
#pragma unroll
                for (int nt = 0; nt < 4; nt++) {
                    int cc = wn * 32 + nt * 8 + 2 * qq;
                    int col2 = wn * 16 + nt * 4 + qq;
                    sH[r * HSTR2 + col2] =
                        h2bits(lrelu(acc[mt][nt][0] + sBla[cc]), lrelu(acc[mt][nt][1] + sBla[cc + 1]));
                    sH[(r + 8) * HSTR2 + col2] =
                        h2bits(lrelu(acc[mt][nt][2] + sBla[cc]), lrelu(acc[mt][nt][3] + sBla[cc + 1]));
#pragma unroll
                    for (int i = 0; i < 4; i++) acc[mt][nt][i] = 0.f;
                }
            }
            // prefetch next (phase,batch) chunk0 while layer B runs
            if (!(p == 1 && bb == 3))
                gatherChunk(pA, sites, bonds, (bb + 1) & 3, sE, sI1, sI2, 0, tid);
            if (bb == 0) cp_wait_n(0);     // WB chunks resident
            __syncthreads();               // H visible (+ WB for bb==0)

            // ---------------- layer B ----------------
#pragma unroll
            for (int c = 0; c < NCH_B; c++)
                mmaChunk(sH + c * 32, HSTR2, sm + OFW + (NCH_A + c) * 4608, acc, wm, wn, grp, qq);

            __syncthreads();
            if (tid < TM) sRed[tid] = 0.f;
            __syncthreads();

            // ---- gate dot ----
#pragma unroll
            for (int mt = 0; mt < 2; mt++) {
                int r = wm * 32 + mt * 16 + grp;
                float d0 = 0.f, d1 = 0.f;
#pragma unroll
                for (int nt = 0; nt < 4; nt++) {
                    int cc = wn * 32 + nt * 8 + 2 * qq;
                    float w0 = sWg[cc], w1 = sWg[cc + 1];
                    d0 += lrelu(acc[mt][nt][0] + sBlb[cc]) * w0
                        + lrelu(acc[mt][nt][1] + sBlb[cc + 1]) * w1;
                    d1 += lrelu(acc[mt][nt][2] + sBlb[cc]) * w0
                        + lrelu(acc[mt][nt][3] + sBlb[cc + 1]) * w1;
                }
                d0 += __shfl_xor_sync(0xffffffffu, d0, 1);
                d0 += __shfl_xor_sync(0xffffffffu, d0, 2);
                d1 += __shfl_xor_sync(0xffffffffu, d1, 1);
                d1 += __shfl_xor_sync(0xffffffffu, d1, 2);
                if (qq == 0) {
                    atomicAdd(&sRed[r], d0);
                    atomicAdd(&sRed[r + 8], d1);
                }
            }
            __syncthreads();

            // ---- gate apply: p0 park g1 in regs; p1 combine + vector-red scatter ----
#pragma unroll
            for (int mt = 0; mt < 2; mt++) {
                int r = wm * 32 + mt * 16 + grp;
                float sig0 = 1.f / (1.f + __expf(-(sRed[r] + bg)));
                float sig1 = 1.f / (1.f + __expf(-(sRed[r + 8] + bg)));
                if (p == 0) {
#pragma unroll
                    for (int nt = 0; nt < 4; nt++) {
                        int cc = wn * 32 + nt * 8 + 2 * qq;
                        int gi = bb * 16 + (mt * 4 + nt) * 2;
                        g1h[gi]     = h2bits(sig0 * lrelu(acc[mt][nt][0] + sBlb[cc]),
                                             sig0 * lrelu(acc[mt][nt][1] + sBlb[cc + 1]));
                        g1h[gi + 1] = h2bits(sig1 * lrelu(acc[mt][nt][2] + sBlb[cc]),
                                             sig1 * lrelu(acc[mt][nt][3] + sBlb[cc + 1]));
                    }
                } else {
                    bool v0 = sE[r] >= 0, v1 = sE[r + 8] >= 0;
                    float* d0p = out + ((size_t)bb * NNODE + sI2[r]) * DOUT;
                    float* d1p = out + ((size_t)bb * NNODE + sI2[r + 8]) * DOUT;
#pragma unroll
                    for (int nt = 0; nt < 4; nt++) {
                        int cc = wn * 32 + nt * 8 + 2 * qq;
                        int gi = bb * 16 + (mt * 4 + nt) * 2;
                        float2 ga = h2f2(g1h[gi]);
                        float2 gb = h2f2(g1h[gi + 1]);
                        if (v0) {
                            red2(d0p + cc,
                                 sig0 * lrelu(acc[mt][nt][0] + sBlb[cc]) + ga.x,
                                 sig0 * lrelu(acc[mt][nt][1] + sBlb[cc + 1]) + ga.y);
                        }
                        if (v1) {
                            red2(d1p + cc,
                                 sig1 * lrelu(acc[mt][nt][2] + sBlb[cc]) + gb.x,
                                 sig1 * lrelu(acc[mt][nt][3] + sBlb[cc + 1]) + gb.y);
                        }
                    }
                }
            }
        } // bb
    } // p
}

// ---------------- launcher ----------------
extern "C" void kernel_launch(void* const* d_in, const int* in_sizes, int n_in,
                              void* d_out, int out_size) {
    (void)in_sizes; (void)n_in;
    const float* sites = (const float*)d_in[0];
    const float* bonds = (const float*)d_in[1];
    const int*   idx1  = (const int*)d_in[2];
    const int*   idx2  = (const int*)d_in[3];
    const int*   uc    = (const int*)d_in[4];
    const float* W1a = (const float*)d_in[5];
    const float* b1a = (const float*)d_in[6];
    const float* W1b = (const float*)d_in[7];
    const float* b1b = (const float*)d_in[8];
    const float* W2a = (const float*)d_in[9];
    const float* b2a = (const float*)d_in[10];
    const float* W2b = (const float*)d_in[11];
    const float* b2b = (const float*)d_in[12];
    const float* Wa1 = (const float*)d_in[13];
    const float* ba1 = (const float*)d_in[14];
    const float* Wa2 = (const float*)d_in[15];
    const float* ba2 = (const float*)d_in[16];
    float* out = (float*)d_out;

    cudaFuncSetAttribute(k_fused, cudaFuncAttributeMaxDynamicSharedMemorySize, SMEM_BYTES);

    k_prep<<<PB_ZERO + PB_HIST + PB_PREPW, 256>>>(out, out_size, uc, W1a, W2a, W1b, W2b);
    k_scan<<<1, 256>>>();
    k_scatter<<<NHB, 256>>>(uc);
    k_fused<<<NTILES, TB, SMEM_BYTES>>>(sites, bonds, idx1, idx2,
                                        b1a, b1b, b2a, b2b,
                                        Wa1, ba1, Wa2, ba2, out);
}

// round 7
// speedup vs baseline: 4.4208x; 1.0932x over previous
#include <cuda_runtime.h>
#include <cuda_fp16.h>
#include <cstdint>

// ---------------- problem constants ----------------
#define BATCH 4
#define NNODE 4096
#define NEDGE 65536
#define DIN   128
#define DBOND 64
#define DOUT  128
#define NT    4
#define DCAT  320

#define TM    128                  // edges per tile
#define TB    256
#define NCH_A 5                    // k-chunks of 64 over DCAT=320
#define NCH_B 2
#define WSTR2 36                   // W row stride (half2/u32 units)
#define WTILE (128*WSTR2)          // 4608 u32 per W chunk
#define ASTR2 36                   // A row stride
#define ACH   (TM*ASTR2)           // 4608 u32 per A chunk
#define HSTR2 68
#define NTILES (NEDGE/TM + NT)     // 516
#define NHB   256

#define PB_ZERO 2048
#define PB_HIST NHB
#define PB_PREPW (2*NT*(NCH_A+NCH_B))

// ---------------- device scratch ----------------
__device__ int g_poff[NT + 1];
__device__ __align__(16) int g_bcnt[NHB * NT];
__device__ __align__(16) int g_bbase[NHB * NT];
__device__ __align__(16) int g_order[NEDGE + NT * TM];
__device__ uint32_t g_WAh[2 * NT * NCH_A * WTILE];
__device__ uint32_t g_WBh[2 * NT * NCH_B * WTILE];

// ---------------- helpers ----------------
__device__ __forceinline__ float lrelu(float x) { return x > 0.f ? x : 0.01f * x; }
__device__ __forceinline__ uint32_t h2bits(float a, float b) {
    __half2 h = __floats2half2_rn(a, b);
    return *reinterpret_cast<uint32_t*>(&h);
}
__device__ __forceinline__ float2 h2f2(uint32_t u) {
    __half2 h = *reinterpret_cast<__half2*>(&u);
    return __half22float2(h);
}
__device__ __forceinline__ uint32_t smem_u32(const void* p) {
    uint32_t a;
    asm("{ .reg .u64 t; cvta.to.shared.u64 t, %1; cvt.u32.u64 %0, t; }" : "=r"(a) : "l"(p));
    return a;
}
__device__ __forceinline__ void cpasync16(uint32_t saddr, const void* g) {
    asm volatile("cp.async.ca.shared.global [%0], [%1], 16;" :: "r"(saddr), "l"(g));
}
#define CP_COMMIT() asm volatile("cp.async.commit_group;" ::: "memory")
#define CP_WAIT0()  asm volatile("cp.async.wait_group 0;" ::: "memory")
__device__ __forceinline__ void red2(float* addr, float a, float b) {
    asm volatile("red.global.add.v2.f32 [%0], {%1, %2};" :: "l"(addr), "f"(a), "f"(b) : "memory");
}
__device__ __forceinline__ void ldsm4(uint32_t& r0, uint32_t& r1, uint32_t& r2, uint32_t& r3,
                                      uint32_t addr) {
    asm volatile("ldmatrix.sync.aligned.m8n8.x4.shared.b16 {%0,%1,%2,%3}, [%4];"
        : "=r"(r0), "=r"(r1), "=r"(r2), "=r"(r3) : "r"(addr));
}
__device__ __forceinline__ void mma16(float* d, uint32_t a0, uint32_t a1, uint32_t a2, uint32_t a3,
                                      uint32_t b0, uint32_t b1) {
    asm volatile(
        "mma.sync.aligned.m16n8k16.row.col.f32.f16.f16.f32 "
        "{%0,%1,%2,%3},{%4,%5,%6,%7},{%8,%9},{%0,%1,%2,%3};"
        : "+f"(d[0]), "+f"(d[1]), "+f"(d[2]), "+f"(d[3])
        : "r"(a0), "r"(a1), "r"(a2), "r"(a3), "r"(b0), "r"(b1));
}

// ---------------- prep kernels ----------------
__global__ void k_prep(float* __restrict__ out, int n_out, const int* __restrict__ uc,
                       const float* __restrict__ W1a, const float* __restrict__ W2a,
                       const float* __restrict__ W1b, const float* __restrict__ W2b) {
    __shared__ int cnt[NT];
    __shared__ float smw[64 * 129];
    const int blk = blockIdx.x;
    const int tid = threadIdx.x;

    if (blk < PB_ZERO) {
        int i = blk * 256 + tid;
        if (i < (n_out >> 2)) ((float4*)out)[i] = make_float4(0.f, 0.f, 0.f, 0.f);
        if (i < (NEDGE + NT * TM) / 4) ((int4*)g_order)[i] = make_int4(-1, -1, -1, -1);
        return;
    }
    if (blk < PB_ZERO + PB_HIST) {
        int hb = blk - PB_ZERO;
        if (tid < NT) cnt[tid] = 0;
        __syncthreads();
        atomicAdd(&cnt[uc[hb * 256 + tid]], 1);
        __syncthreads();
        if (tid < NT) g_bcnt[hb * NT + tid] = cnt[tid];
        return;
    }
    int wb = blk - PB_ZERO - PB_HIST;
    bool isA = wb < 2 * NT * NCH_A;
    int c, pt;
    if (isA) { c = wb % NCH_A; pt = wb / NCH_A; }
    else     { int j = wb - 2 * NT * NCH_A; c = j % NCH_B; pt = j / NCH_B; }
    int t = pt & 3, p = pt >> 2;
    int ld = isA ? DCAT : DOUT;
    const float* W = isA ? (p ? W2a : W1a) : (p ? W2b : W1b);
#pragma unroll
    for (int i = 0; i < 32; i++) {
        int lin = tid + 256 * i;
        int k = lin >> 7, n = lin & 127;
        smw[k * 129 + n] = W[((size_t)t * ld + c * 64 + k) * DOUT + n];
    }
    __syncthreads();
    uint32_t* dst = isA ? (g_WAh + (size_t)(pt * NCH_A + c) * WTILE)
                        : (g_WBh + (size_t)(pt * NCH_B + c) * WTILE);
#pragma unroll
    for (int i = 0; i < 16; i++) {
        int lin = tid + 256 * i;
        int n = lin >> 5, k2 = lin & 31;
        dst[n * WSTR2 + k2] = h2bits(smw[(2 * k2) * 129 + n], smw[(2 * k2 + 1) * 129 + n]);
    }
}

__global__ void k_scan() {
    __shared__ int wsum[8][NT];
    __shared__ int tot[NT];
    int tid = threadIdx.x, lane = tid & 31, w = tid >> 5;
    int4 v = ((const int4*)g_bcnt)[tid];
    int4 orig = v;
#pragma unroll
    for (int d = 1; d < 32; d <<= 1) {
        int x = __shfl_up_sync(~0u, v.x, d), y = __shfl_up_sync(~0u, v.y, d);
        int z = __shfl_up_sync(~0u, v.z, d), q = __shfl_up_sync(~0u, v.w, d);
        if (lane >= d) { v.x += x; v.y += y; v.z += z; v.w += q; }
    }
    if (lane == 31) { wsum[w][0] = v.x; wsum[w][1] = v.y; wsum[w][2] = v.z; wsum[w][3] = v.w; }
    __syncthreads();
    if (tid == 0) {
        int a0 = 0, a1 = 0, a2 = 0, a3 = 0;
        for (int i = 0; i < 8; i++) {
            int t0 = wsum[i][0], t1 = wsum[i][1], t2 = wsum[i][2], t3 = wsum[i][3];
            wsum[i][0] = a0; wsum[i][1] = a1; wsum[i][2] = a2; wsum[i][3] = a3;
            a0 += t0; a1 += t1; a2 += t2; a3 += t3;
        }
        tot[0] = a0; tot[1] = a1; tot[2] = a2; tot[3] = a3;
    }
    __syncthreads();
    int e0 = v.x + wsum[w][0] - orig.x;
    int e1 = v.y + wsum[w][1] - orig.y;
    int e2 = v.z + wsum[w][2] - orig.z;
    int e3 = v.w + wsum[w][3] - orig.w;
    int p0 = 0;
    int p1 = p0 + ((tot[0] + TM - 1) / TM) * TM;
    int p2 = p1 + ((tot[1] + TM - 1) / TM) * TM;
    int p3 = p2 + ((tot[2] + TM - 1) / TM) * TM;
    int p4 = p3 + ((tot[3] + TM - 1) / TM) * TM;
    int4 bb; bb.x = p0 + e0; bb.y = p1 + e1; bb.z = p2 + e2; bb.w = p3 + e3;
    ((int4*)g_bbase)[tid] = bb;
    if (tid == 0) {
        g_poff[0] = p0; g_poff[1] = p1; g_poff[2] = p2; g_poff[3] = p3; g_poff[4] = p4;
    }
}

__global__ void k_scatter(const int* __restrict__ uc) {
    __shared__ int base[NT];
    __shared__ int cur[NT];
    int tid = threadIdx.x;
    if (tid < NT) { base[tid] = g_bbase[blockIdx.x * NT + tid]; cur[tid] = 0; }
    __syncthreads();
    int e = blockIdx.x * 256 + tid;
    int t = uc[e];
    int pos = atomicAdd(&cur[t], 1);
    g_order[base[t] + pos] = e;
}

// ---------------- fused kernel smem layout (u32 units) ----------------
#define OFA    0                       // 5 x 4608 = 23040  (A resident, fp16)
#define OFW    23040                   // 2 x 4608 = 9216   (W double buffer)
#define OFH    32256                   // 128 x 68 = 8704
#define OFRED  40960
#define OFBIAS 41088                   // 6 x 128
#define OFE    41856
#define OFI1   41984
#define OFI2   42112
#define SMEM_U32 42240
#define SMEM_BYTES (SMEM_U32 * 4)      // 168960

__device__ __forceinline__ void issueW(uint32_t sdst, const uint32_t* __restrict__ g, int tid) {
    const uint4* gs = (const uint4*)g;
#pragma unroll
    for (int i = 0; i < 5; i++) {
        int lin = tid + TB * i;
        if (lin < 1152) cpasync16(sdst + lin * 16, gs + lin);
    }
    CP_COMMIT();
}

__device__ __forceinline__ void gatherChunk(float4* pA, const float* __restrict__ sites,
                                            const float* __restrict__ bonds, int b,
                                            const int* sE, const int* sI1, const int* sI2,
                                            int c, int tid) {
#pragma unroll
    for (int i = 0; i < 8; i++) {
        int lin = tid + TB * i;
        int row = lin >> 4, col = (lin & 15) << 2;
        const float* src;
        if (c < 2)      src = sites + ((size_t)b * NNODE + sI1[row]) * DIN + c * 64 + col;
        else if (c < 4) src = sites + ((size_t)b * NNODE + sI2[row]) * DIN + (c - 2) * 64 + col;
        else { int e = sE[row]; if (e < 0) e = 0;
               src = bonds + ((size_t)b * NEDGE + e) * DBOND + col; }
        pA[i] = *(const float4*)src;
    }
}

__device__ __forceinline__ void stageChunk(uint32_t* __restrict__ Ab, const float4* pA, int tid) {
#pragma unroll
    for (int i = 0; i < 8; i++) {
        int lin = tid + TB * i;
        int row = lin >> 4, j = (lin & 15) << 1;
        uint2 v;
        v.x = h2bits(pA[i].x, pA[i].y);
        v.y = h2bits(pA[i].z, pA[i].w);
        *(uint2*)(Ab + row * ASTR2 + j) = v;
    }
}

// one k=64 chunk: LDSM operands, 32 k-halves; warp tile 64x32
__device__ __forceinline__ void mmaChunkL(uint32_t aAddr, int astrB, uint32_t wAddr,
                                          float acc[4][4][4]) {
#pragma unroll
    for (int kk = 0; kk < 4; kk++) {
        const uint32_t kb = kk * 32;   // bytes (8 u32)
        uint32_t b00, b01, b10, b11, b20, b21, b30, b31;
        ldsm4(b00, b01, b10, b11, wAddr + kb);                    // nt0, nt1
        ldsm4(b20, b21, b30, b31, wAddr + 16 * WSTR2 * 4 + kb);   // nt2, nt3
#pragma unroll
        for (int mt = 0; mt < 4; mt++) {
            uint32_t a0, a1, a2, a3;
            ldsm4(a0, a1, a2, a3, aAddr + mt * 16 * astrB + kb);
            mma16(acc[mt][0], a0, a1, a2, a3, b00, b01);
            mma16(acc[mt][1], a0, a1, a2, a3, b10, b11);
            mma16(acc[mt][2], a0, a1, a2, a3, b20, b21);
            mma16(acc[mt][3], a0, a1, a2, a3, b30, b31);
        }
    }
}

__global__ void __launch_bounds__(TB) k_fused(
    const float* __restrict__ sites, const float* __restrict__ bonds,
    const int* __restrict__ idx1, const int* __restrict__ idx2,
    const float* __restrict__ b1a, const float* __restrict__ b1b,
    const float* __restrict__ b2a, const float* __restrict__ b2b,
    const float* __restrict__ Wa1, const float* __restrict__ ba1,
    const float* __restrict__ Wa2, const float* __restrict__ ba2,
    float* __restrict__ out)
{
    extern __shared__ uint32_t sm[];
    uint32_t* sH = sm + OFH;
    float* sRed  = (float*)(sm + OFRED);
    float* sBias = (float*)(sm + OFBIAS);
    int* sE  = (int*)(sm + OFE);
    int* sI1 = (int*)(sm + OFI1);
    int* sI2 = (int*)(sm + OFI2);

    const int tile  = blockIdx.x;
    const int start = tile * TM;
    if (start >= g_poff[NT]) return;
    int t = 0;
#pragma unroll
    for (int i = 1; i < NT; i++) if (start >= g_poff[i]) t = i;

    const int tid  = threadIdx.x;
    const int lane = tid & 31;
    const int wid  = tid >> 5;
    const int wm   = wid & 1;       // 64-row half
    const int wn   = wid >> 1;      // 32-col quarter
    const int grp  = lane >> 2;
    const int qq   = lane & 3;

    if (tid < TM) {
        int e = g_order[start + tid];
        sE[tid] = e;
        int es = e < 0 ? 0 : e;
        sI1[tid] = idx1[es];
        sI2[tid] = idx2[es];
    }
    if (tid < 128) {
        sBias[0 * 128 + tid] = b1a[t * DOUT + tid];
        sBias[1 * 128 + tid] = b1b[t * DOUT + tid];
        sBias[2 * 128 + tid] = Wa1[tid];
        sBias[3 * 128 + tid] = b2a[t * DOUT + tid];
        sBias[4 * 128 + tid] = b2b[t * DOUT + tid];
        sBias[5 * 128 + tid] = Wa2[tid];
    }
    __syncthreads();

    // ldmatrix per-thread lane offsets
    const int rA = wm * 64 + (lane & 7) + ((lane >> 3) & 1) * 8;
    const int nB = (lane & 7) + ((lane >> 4) & 1) * 8;
    const uint32_t sb = smem_u32(sm);
    const uint32_t aBase = sb + (uint32_t)(rA * ASTR2 + (lane >> 4) * 4) * 4;    // + c*ACH*4
    const uint32_t hBase = sb + (uint32_t)(OFH + rA * HSTR2 + (lane >> 4) * 4) * 4;
    const uint32_t wBase = sb + (uint32_t)(OFW + (wn * 32 + nB) * WSTR2 + ((lane >> 3) & 1) * 4) * 4;

    const int bb0 = blockIdx.y * 2;
    const float bg1 = ba1[0], bg2 = ba2[0];

    float4 pA[8];
    uint32_t g1h[32];

    // prologue: first W chunk (p=0) + gather chunk0 of bb0
    issueW(sb + OFW * 4, g_WAh + (size_t)((0 * NT + t) * NCH_A) * WTILE, tid);
    gatherChunk(pA, sites, bonds, bb0, sE, sI1, sI2, 0, tid);

#pragma unroll 1
    for (int it = 0; it < 4; ++it) {
        const int p  = it & 1;
        const int bb = bb0 + (it >> 1);
        const uint32_t* gWA = g_WAh + (size_t)((p * NT + t) * NCH_A) * WTILE;
        const uint32_t* gWB = g_WBh + (size_t)((p * NT + t) * NCH_B) * WTILE;
        const float* sBla = sBias + (p * 3 + 0) * 128;
        const float* sBlb = sBias + (p * 3 + 1) * 128;
        const float* sWg  = sBias + (p * 3 + 2) * 128;
        const float bg = p ? bg2 : bg1;

        float acc[4][4][4];
#pragma unroll
        for (int mt = 0; mt < 4; mt++)
#pragma unroll
            for (int nt = 0; nt < 4; nt++)
#pragma unroll
                for (int i = 0; i < 4; i++) acc[mt][nt][i] = 0.f;

        // ---------------- layer A ----------------
#pragma unroll
        for (int c = 0; c < NCH_A; c++) {
            if (p == 0) stageChunk(sm + OFA + c * ACH, pA, tid);
            CP_WAIT0();
            __syncthreads();
            if (c + 1 < NCH_A) {
                issueW(sb + (OFW + ((c + 1) & 1) * WTILE) * 4, gWA + (size_t)(c + 1) * WTILE, tid);
                if (p == 0) gatherChunk(pA, sites, bonds, bb, sE, sI1, sI2, c + 1, tid);
            } else {
                issueW(sb + (OFW + WTILE) * 4, gWB, tid);      // layer-B W0 -> buf1
            }
            mmaChunkL(aBase + (uint32_t)(c * ACH) * 4, ASTR2 * 4,
                      wBase + (uint32_t)((c & 1) * WTILE) * 4, acc);
        }
        __syncthreads();   // all layer-A MMA done

        // ---- epilogue A: H = fp16(lrelu(acc + bla)) ----
#pragma unroll
        for (int mt = 0; mt < 4; mt++) {
            int r = wm * 64 + mt * 16 + grp;
#pragma unroll
            for (int nt = 0; nt < 4; nt++) {
                int cc = wn * 32 + nt * 8 + 2 * qq;
                int col2 = wn * 16 + nt * 4 + qq;
                sH[r * HSTR2 + col2] =
                    h2bits(lrelu(acc[mt][nt][0] + sBla[cc]), lrelu(acc[mt][nt][1] + sBla[cc + 1]));
                sH[(r + 8) * HSTR2 + col2] =
                    h2bits(lrelu(acc[mt][nt][2] + sBla[cc]), lrelu(acc[mt][nt][3] + sBla[cc + 1]));
#pragma unroll
                for (int i = 0; i < 4; i++) acc[mt][nt][i] = 0.f;
            }
        }
        issueW(sb + OFW * 4, gWB + WTILE, tid);                // layer-B W1 -> buf0
        CP_WAIT0();
        __syncthreads();   // H visible + layer-B weights resident

        // ---------------- layer B ----------------
        mmaChunkL(hBase,       HSTR2 * 4, wBase + (uint32_t)WTILE * 4, acc);
        mmaChunkL(hBase + 128, HSTR2 * 4, wBase,                       acc);
        __syncthreads();   // layer-B W buffers free

        if (it < 3) {      // prefetch next phase's first W chunk -> buf0
            int pn = (it + 1) & 1;
            issueW(sb + OFW * 4, g_WAh + (size_t)((pn * NT + t) * NCH_A) * WTILE, tid);
        }
        if (it == 1)       // prefetch next batch's A chunk0 under the gate
            gatherChunk(pA, sites, bonds, bb0 + 1, sE, sI1, sI2, 0, tid);
        if (tid < TM) sRed[tid] = 0.f;
        __syncthreads();

        // ---- gate dot ----
#pragma unroll
        for (int mt = 0; mt < 4; mt++) {
            int r = wm * 64 + mt * 16 + grp;
            float d0 = 0.f, d1 = 0.f;
#pragma unroll
            for (int nt = 0; nt < 4; nt++) {
                int cc = wn * 32 + nt * 8 + 2 * qq;
                float w0 = sWg[cc], w1 = sWg[cc + 1];
                d0 += lrelu(acc[mt][nt][0] + sBlb[cc]) * w0
                    + lrelu(acc[mt][nt][1] + sBlb[cc + 1]) * w1;
                d1 += lrelu(acc[mt][nt][2] + sBlb[cc]) * w0
                    + lrelu(acc[mt][nt][3] + sBlb[cc + 1]) * w1;
            }
            d0 += __shfl_xor_sync(0xffffffffu, d0, 1);
            d0 += __shfl_xor_sync(0xffffffffu, d0, 2);
            d1 += __shfl_xor_sync(0xffffffffu, d1, 1);
            d1 += __shfl_xor_sync(0xffffffffu, d1, 2);
            if (qq == 0) {
                atomicAdd(&sRed[r], d0);
                atomicAdd(&sRed[r + 8], d1);
            }
        }
        __syncthreads();

        // ---- gate apply: p0 park g1 in regs; p1 combine + vector-red scatter ----
#pragma unroll
        for (int mt = 0; mt < 4; mt++) {
            int r = wm * 64 + mt * 16 + grp;
            float sig0 = 1.f / (1.f + __expf(-(sRed[r] + bg)));
            float sig1 = 1.f / (1.f + __expf(-(sRed[r + 8] + bg)));
            if (p == 0) {
#pragma unroll
                for (int nt = 0; nt < 4; nt++) {
                    int cc = wn * 32 + nt * 8 + 2 * qq;
                    int gi = (mt * 4 + nt) * 2;
                    g1h[gi]     = h2bits(sig0 * lrelu(acc[mt][nt][0] + sBlb[cc]),
                                         sig0 * lrelu(acc[mt][nt][1] + sBlb[cc + 1]));
                    g1h[gi + 1] = h2bits(sig1 * lrelu(acc[mt][nt][2] + sBlb[cc]),
                                         sig1 * lrelu(acc[mt][nt][3] + sBlb[cc + 1]));
                }
            } else {
                bool v0 = sE[r] >= 0, v1 = sE[r + 8] >= 0;
                float* d0p = out + ((size_t)bb * NNODE + sI2[r]) * DOUT;
                float* d1p = out + ((size_t)bb * NNODE + sI2[r + 8]) * DOUT;
#pragma unroll
                for (int nt = 0; nt < 4; nt++) {
                    int cc = wn * 32 + nt * 8 + 2 * qq;
                    int gi = (mt * 4 + nt) * 2;
                    float2 ga = h2f2(g1h[gi]);
                    float2 gb = h2f2(g1h[gi + 1]);
                    if (v0) {
                        red2(d0p + cc,
                             sig0 * lrelu(acc[mt][nt][0] + sBlb[cc]) + ga.x,
                             sig0 * lrelu(acc[mt][nt][1] + sBlb[cc + 1]) + ga.y);
                    }
                    if (v1) {
                        red2(d1p + cc,
                             sig1 * lrelu(acc[mt][nt][2] + sBlb[cc]) + gb.x,
                             sig1 * lrelu(acc[mt][nt][3] + sBlb[cc + 1]) + gb.y);
                    }
                }
            }
        }
    } // it
}

// ---------------- launcher ----------------
extern "C" void kernel_launch(void* const* d_in, const int* in_sizes, int n_in,
                              void* d_out, int out_size) {
    (void)in_sizes; (void)n_in;
    const float* sites = (const float*)d_in[0];
    const float* bonds = (const float*)d_in[1];
    const int*   idx1  = (const int*)d_in[2];
    const int*   idx2  = (const int*)d_in[3];
    const int*   uc    = (const int*)d_in[4];
    const float* W1a = (const float*)d_in[5];
    const float* b1a = (const float*)d_in[6];
    const float* W1b = (const float*)d_in[7];
    const float* b1b = (const float*)d_in[8];
    const float* W2a = (const float*)d_in[9];
    const float* b2a = (const float*)d_in[10];
    const float* W2b = (const float*)d_in[11];
    const float* b2b = (const float*)d_in[12];
    const float* Wa1 = (const float*)d_in[13];
    const float* ba1 = (const float*)d_in[14];
    const float* Wa2 = (const float*)d_in[15];
    const float* ba2 = (const float*)d_in[16];
    float* out = (float*)d_out;

    cudaFuncSetAttribute(k_fused, cudaFuncAttributeMaxDynamicSharedMemorySize, SMEM_BYTES);

    k_prep<<<PB_ZERO + PB_HIST + PB_PREPW, 256>>>(out, out_size, uc, W1a, W2a, W1b, W2b);
    k_scan<<<1, 256>>>();
    k_scatter<<<NHB, 256>>>(uc);
    dim3 grid(NTILES, BATCH / 2);
    k_fused<<<grid, TB, SMEM_BYTES>>>(sites, bonds, idx1, idx2,
                                      b1a, b1b, b2a, b2b,
                                      Wa1, ba1, Wa2, ba2, out);
}

// round 8
// speedup vs baseline: 4.7317x; 1.0703x over previous
#include <cuda_runtime.h>
#include <cuda_fp16.h>
#include <cstdint>

// ---------------- problem constants ----------------
#define BATCH 4
#define NNODE 4096
#define NEDGE 65536
#define DIN   128
#define DBOND 64
#define DOUT  128
#define NT    4
#define DCAT  320

#define TM    128                  // edges per tile
#define TB    512                  // 16 warps
#define NCH_A 5                    // k-chunks of 64 over DCAT=320
#define NCH_B 2
#define WSTR2 36                   // W row stride (half2/u32 units)
#define WTILE (128*WSTR2)          // 4608 u32 per W chunk
#define ASTR2 36                   // A row stride
#define ACH   (TM*ASTR2)           // 4608 u32 per A chunk
#define HSTR2 68
#define NTILES (NEDGE/TM + NT)     // 516
#define NHB   256

#define PB_ZERO 2048
#define PB_HIST NHB
#define PB_PREPW (2*NT*(NCH_A+NCH_B))

// ---------------- device scratch ----------------
__device__ int g_poff[NT + 1];
__device__ __align__(16) int g_bcnt[NHB * NT];
__device__ __align__(16) int g_bbase[NHB * NT];
__device__ __align__(16) int g_order[NEDGE + NT * TM];
__device__ uint32_t g_WAh[2 * NT * NCH_A * WTILE];
__device__ uint32_t g_WBh[2 * NT * NCH_B * WTILE];

// ---------------- helpers ----------------
__device__ __forceinline__ float lrelu(float x) { return x > 0.f ? x : 0.01f * x; }
__device__ __forceinline__ uint32_t h2bits(float a, float b) {
    __half2 h = __floats2half2_rn(a, b);
    return *reinterpret_cast<uint32_t*>(&h);
}
__device__ __forceinline__ float2 h2f2(uint32_t u) {
    __half2 h = *reinterpret_cast<__half2*>(&u);
    return __half22float2(h);
}
__device__ __forceinline__ uint32_t smem_u32(const void* p) {
    uint32_t a;
    asm("{ .reg .u64 t; cvta.to.shared.u64 t, %1; cvt.u32.u64 %0, t; }" : "=r"(a) : "l"(p));
    return a;
}
__device__ __forceinline__ void cpasync16(uint32_t saddr, const void* g) {
    asm volatile("cp.async.ca.shared.global [%0], [%1], 16;" :: "r"(saddr), "l"(g));
}
#define CP_COMMIT() asm volatile("cp.async.commit_group;" ::: "memory")
#define CP_WAIT0()  asm volatile("cp.async.wait_group 0;" ::: "memory")
__device__ __forceinline__ void red2(float* addr, float a, float b) {
    asm volatile("red.global.add.v2.f32 [%0], {%1, %2};" :: "l"(addr), "f"(a), "f"(b) : "memory");
}
__device__ __forceinline__ void ldsm4(uint32_t& r0, uint32_t& r1, uint32_t& r2, uint32_t& r3,
                                      uint32_t addr) {
    asm volatile("ldmatrix.sync.aligned.m8n8.x4.shared.b16 {%0,%1,%2,%3}, [%4];"
        : "=r"(r0), "=r"(r1), "=r"(r2), "=r"(r3) : "r"(addr));
}
__device__ __forceinline__ void mma16(float* d, uint32_t a0, uint32_t a1, uint32_t a2, uint32_t a3,
                                      uint32_t b0, uint32_t b1) {
    asm volatile(
        "mma.sync.aligned.m16n8k16.row.col.f32.f16.f16.f32 "
        "{%0,%1,%2,%3},{%4,%5,%6,%7},{%8,%9},{%0,%1,%2,%3};"
        : "+f"(d[0]), "+f"(d[1]), "+f"(d[2]), "+f"(d[3])
        : "r"(a0), "r"(a1), "r"(a2), "r"(a3), "r"(b0), "r"(b1));
}

// ---------------- prep kernels ----------------
__global__ void k_prep(float* __restrict__ out, int n_out, const int* __restrict__ uc,
                       const float* __restrict__ W1a, const float* __restrict__ W2a,
                       const float* __restrict__ W1b, const float* __restrict__ W2b) {
    __shared__ int cnt[NT];
    __shared__ float smw[64 * 129];
    const int blk = blockIdx.x;
    const int tid = threadIdx.x;

    if (blk < PB_ZERO) {
        int i = blk * 256 + tid;
        if (i < (n_out >> 2)) ((float4*)out)[i] = make_float4(0.f, 0.f, 0.f, 0.f);
        if (i < (NEDGE + NT * TM) / 4) ((int4*)g_order)[i] = make_int4(-1, -1, -1, -1);
        return;
    }
    if (blk < PB_ZERO + PB_HIST) {
        int hb = blk - PB_ZERO;
        if (tid < NT) cnt[tid] = 0;
        __syncthreads();
        atomicAdd(&cnt[uc[hb * 256 + tid]], 1);
        __syncthreads();
        if (tid < NT) g_bcnt[hb * NT + tid] = cnt[tid];
        return;
    }
    int wb = blk - PB_ZERO - PB_HIST;
    bool isA = wb < 2 * NT * NCH_A;
    int c, pt;
    if (isA) { c = wb % NCH_A; pt = wb / NCH_A; }
    else     { int j = wb - 2 * NT * NCH_A; c = j % NCH_B; pt = j / NCH_B; }
    int t = pt & 3, p = pt >> 2;
    int ld = isA ? DCAT : DOUT;
    const float* W = isA ? (p ? W2a : W1a) : (p ? W2b : W1b);
#pragma unroll
    for (int i = 0; i < 32; i++) {
        int lin = tid + 256 * i;
        int k = lin >> 7, n = lin & 127;
        smw[k * 129 + n] = W[((size_t)t * ld + c * 64 + k) * DOUT + n];
    }
    __syncthreads();
    uint32_t* dst = isA ? (g_WAh + (size_t)(pt * NCH_A + c) * WTILE)
                        : (g_WBh + (size_t)(pt * NCH_B + c) * WTILE);
#pragma unroll
    for (int i = 0; i < 16; i++) {
        int lin = tid + 256 * i;
        int n = lin >> 5, k2 = lin & 31;
        dst[n * WSTR2 + k2] = h2bits(smw[(2 * k2) * 129 + n], smw[(2 * k2 + 1) * 129 + n]);
    }
}

__global__ void k_scan() {
    __shared__ int wsum[8][NT];
    __shared__ int tot[NT];
    int tid = threadIdx.x, lane = tid & 31, w = tid >> 5;
    int4 v = ((const int4*)g_bcnt)[tid];
    int4 orig = v;
#pragma unroll
    for (int d = 1; d < 32; d <<= 1) {
        int x = __shfl_up_sync(~0u, v.x, d), y = __shfl_up_sync(~0u, v.y, d);
        int z = __shfl_up_sync(~0u, v.z, d), q = __shfl_up_sync(~0u, v.w, d);
        if (lane >= d) { v.x += x; v.y += y; v.z += z; v.w += q; }
    }
    if (lane == 31) { wsum[w][0] = v.x; wsum[w][1] = v.y; wsum[w][2] = v.z; wsum[w][3] = v.w; }
    __syncthreads();
    if (tid == 0) {
        int a0 = 0, a1 = 0, a2 = 0, a3 = 0;
        for (int i = 0; i < 8; i++) {
            int t0 = wsum[i][0], t1 = wsum[i][1], t2 = wsum[i][2], t3 = wsum[i][3];
            wsum[i][0] = a0; wsum[i][1] = a1; wsum[i][2] = a2; wsum[i][3] = a3;
            a0 += t0; a1 += t1; a2 += t2; a3 += t3;
        }
        tot[0] = a0; tot[1] = a1; tot[2] = a2; tot[3] = a3;
    }
    __syncthreads();
    int e0 = v.x + wsum[w][0] - orig.x;
    int e1 = v.y + wsum[w][1] - orig.y;
    int e2 = v.z + wsum[w][2] - orig.z;
    int e3 = v.w + wsum[w][3] - orig.w;
    int p0 = 0;
    int p1 = p0 + ((tot[0] + TM - 1) / TM) * TM;
    int p2 = p1 + ((tot[1] + TM - 1) / TM) * TM;
    int p3 = p2 + ((tot[2] + TM - 1) / TM) * TM;
    int p4 = p3 + ((tot[3] + TM - 1) / TM) * TM;
    int4 bb; bb.x = p0 + e0; bb.y = p1 + e1; bb.z = p2 + e2; bb.w = p3 + e3;
    ((int4*)g_bbase)[tid] = bb;
    if (tid == 0) {
        g_poff[0] = p0; g_poff[1] = p1; g_poff[2] = p2; g_poff[3] = p3; g_poff[4] = p4;
    }
}

__global__ void k_scatter(const int* __restrict__ uc) {
    __shared__ int base[NT];
    __shared__ int cur[NT];
    int tid = threadIdx.x;
    if (tid < NT) { base[tid] = g_bbase[blockIdx.x * NT + tid]; cur[tid] = 0; }
    __syncthreads();
    int e = blockIdx.x * 256 + tid;
    int t = uc[e];
    int pos = atomicAdd(&cur[t], 1);
    g_order[base[t] + pos] = e;
}

// ---------------- fused kernel smem layout (u32 units) ----------------
#define OFA    0                       // 5 x 4608 = 23040  (A resident, fp16)
#define OFW    23040                   // 2 x 4608 = 9216   (W double buffer)
#define OFH    32256                   // 128 x 68 = 8704
#define OFRED  40960
#define OFBIAS 41088                   // 6 x 128
#define OFE    41856
#define OFI1   41984
#define OFI2   42112
#define SMEM_U32 42240
#define SMEM_BYTES (SMEM_U32 * 4)      // 168960

__device__ __forceinline__ void issueW(uint32_t sdst, const uint32_t* __restrict__ g, int tid) {
    const uint4* gs = (const uint4*)g;
#pragma unroll
    for (int i = 0; i < 3; i++) {
        int lin = tid + TB * i;
        if (lin < 1152) cpasync16(sdst + lin * 16, gs + lin);
    }
    CP_COMMIT();
}

__device__ __forceinline__ void gatherChunk(float4* pA, const float* __restrict__ sites,
                                            const float* __restrict__ bonds, int b,
                                            const int* sE, const int* sI1, const int* sI2,
                                            int c, int tid) {
#pragma unroll
    for (int i = 0; i < 4; i++) {
        int lin = tid + TB * i;
        int row = lin >> 4, col = (lin & 15) << 2;
        const float* src;
        if (c < 2)      src = sites + ((size_t)b * NNODE + sI1[row]) * DIN + c * 64 + col;
        else if (c < 4) src = sites + ((size_t)b * NNODE + sI2[row]) * DIN + (c - 2) * 64 + col;
        else { int e = sE[row]; if (e < 0) e = 0;
               src = bonds + ((size_t)b * NEDGE + e) * DBOND + col; }
        pA[i] = *(const float4*)src;
    }
}

__device__ __forceinline__ void stageChunk(uint32_t* __restrict__ Ab, const float4* pA, int tid) {
#pragma unroll
    for (int i = 0; i < 4; i++) {
        int lin = tid + TB * i;
        int row = lin >> 4, j = (lin & 15) << 1;
        uint2 v;
        v.x = h2bits(pA[i].x, pA[i].y);
        v.y = h2bits(pA[i].z, pA[i].w);
        *(uint2*)(Ab + row * ASTR2 + j) = v;
    }
}

// one k=64 chunk: LDSM operands; warp tile 32x32
__device__ __forceinline__ void mmaChunkL(uint32_t aAddr, int astrB, uint32_t wAddr,
                                          float acc[2][4][4]) {
#pragma unroll
    for (int kk = 0; kk < 4; kk++) {
        const uint32_t kb = kk * 32;   // bytes (8 u32)
        uint32_t b00, b01, b10, b11, b20, b21, b30, b31;
        ldsm4(b00, b01, b10, b11, wAddr + kb);                    // n cols +0..15
        ldsm4(b20, b21, b30, b31, wAddr + 16 * WSTR2 * 4 + kb);   // n cols +16..31
#pragma unroll
        for (int mt = 0; mt < 2; mt++) {
            uint32_t a0, a1, a2, a3;
            ldsm4(a0, a1, a2, a3, aAddr + mt * 16 * astrB + kb);
            mma16(acc[mt][0], a0, a1, a2, a3, b00, b01);
            mma16(acc[mt][1], a0, a1, a2, a3, b10, b11);
            mma16(acc[mt][2], a0, a1, a2, a3, b20, b21);
            mma16(acc[mt][3], a0, a1, a2, a3, b30, b31);
        }
    }
}

__global__ void __launch_bounds__(TB) k_fused(
    const float* __restrict__ sites, const float* __restrict__ bonds,
    const int* __restrict__ idx1, const int* __restrict__ idx2,
    const float* __restrict__ b1a, const float* __restrict__ b1b,
    const float* __restrict__ b2a, const float* __restrict__ b2b,
    const float* __restrict__ Wa1, const float* __restrict__ ba1,
    const float* __restrict__ Wa2, const float* __restrict__ ba2,
    float* __restrict__ out)
{
    extern __shared__ uint32_t sm[];
    uint32_t* sH = sm + OFH;
    float* sRed  = (float*)(sm + OFRED);
    float* sBias = (float*)(sm + OFBIAS);
    int* sE  = (int*)(sm + OFE);
    int* sI1 = (int*)(sm + OFI1);
    int* sI2 = (int*)(sm + OFI2);

    const int tile  = blockIdx.x;
    const int start = tile * TM;
    if (start >= g_poff[NT]) return;
    int t = 0;
#pragma unroll
    for (int i = 1; i < NT; i++) if (start >= g_poff[i]) t = i;

    const int tid  = threadIdx.x;
    const int lane = tid & 31;
    const int wid  = tid >> 5;
    const int wm   = wid & 3;       // 32-row quarter
    const int wn   = wid >> 2;      // 32-col quarter
    const int grp  = lane >> 2;
    const int qq   = lane & 3;

    if (tid < TM) {
        int e = g_order[start + tid];
        sE[tid] = e;
        int es = e < 0 ? 0 : e;
        sI1[tid] = idx1[es];
        sI2[tid] = idx2[es];
    }
    if (tid < 128) {
        sBias[0 * 128 + tid] = b1a[t * DOUT + tid];
        sBias[1 * 128 + tid] = b1b[t * DOUT + tid];
        sBias[2 * 128 + tid] = Wa1[tid];
        sBias[3 * 128 + tid] = b2a[t * DOUT + tid];
        sBias[4 * 128 + tid] = b2b[t * DOUT + tid];
        sBias[5 * 128 + tid] = Wa2[tid];
    }
    __syncthreads();

    // ldmatrix per-thread lane offsets
    const int rA = wm * 32 + (lane & 7) + ((lane >> 3) & 1) * 8;
    const int nB = (lane & 7) + ((lane >> 4) & 1) * 8;
    const uint32_t sb = smem_u32(sm);
    const uint32_t aBase = sb + (uint32_t)(rA * ASTR2 + (lane >> 4) * 4) * 4;    // + c*ACH*4
    const uint32_t hBase = sb + (uint32_t)(OFH + rA * HSTR2 + (lane >> 4) * 4) * 4;
    const uint32_t wBase = sb + (uint32_t)(OFW + (wn * 32 + nB) * WSTR2 + ((lane >> 3) & 1) * 4) * 4;

    const int bb0 = blockIdx.y * 2;
    const float bg1 = ba1[0], bg2 = ba2[0];

    float4 pA[4];
    uint32_t g1h[16];

    // prologue: first W chunk (p=0) + gather chunk0 of bb0
    issueW(sb + OFW * 4, g_WAh + (size_t)((0 * NT + t) * NCH_A) * WTILE, tid);
    gatherChunk(pA, sites, bonds, bb0, sE, sI1, sI2, 0, tid);

#pragma unroll 1
    for (int it = 0; it < 4; ++it) {
        const int p  = it & 1;
        const int bb = bb0 + (it >> 1);
        const uint32_t* gWA = g_WAh + (size_t)((p * NT + t) * NCH_A) * WTILE;
        const uint32_t* gWB = g_WBh + (size_t)((p * NT + t) * NCH_B) * WTILE;
        const float* sBla = sBias + (p * 3 + 0) * 128;
        const float* sBlb = sBias + (p * 3 + 1) * 128;
        const float* sWg  = sBias + (p * 3 + 2) * 128;
        const float bg = p ? bg2 : bg1;

        float acc[2][4][4];
#pragma unroll
        for (int mt = 0; mt < 2; mt++)
#pragma unroll
            for (int nt = 0; nt < 4; nt++)
#pragma unroll
                for (int i = 0; i < 4; i++) acc[mt][nt][i] = 0.f;

        // ---------------- layer A ----------------
#pragma unroll
        for (int c = 0; c < NCH_A; c++) {
            if (p == 0) stageChunk(sm + OFA + c * ACH, pA, tid);
            CP_WAIT0();
            __syncthreads();
            if (c + 1 < NCH_A) {
                issueW(sb + (OFW + ((c + 1) & 1) * WTILE) * 4, gWA + (size_t)(c + 1) * WTILE, tid);
                if (p == 0) gatherChunk(pA, sites, bonds, bb, sE, sI1, sI2, c + 1, tid);
            } else {
                issueW(sb + (OFW + WTILE) * 4, gWB, tid);      // layer-B W0 -> buf1
            }
            mmaChunkL(aBase + (uint32_t)(c * ACH) * 4, ASTR2 * 4,
                      wBase + (uint32_t)((c & 1) * WTILE) * 4, acc);
        }
        __syncthreads();   // all layer-A MMA done

        // ---- epilogue A: H = fp16(lrelu(acc + bla)) ----
#pragma unroll
        for (int mt = 0; mt < 2; mt++) {
            int r = wm * 32 + mt * 16 + grp;
#pragma unroll
            for (int nt = 0; nt < 4; nt++) {
                int cc = wn * 32 + nt * 8 + 2 * qq;
                int col2 = wn * 16 + nt * 4 + qq;
                sH[r * HSTR2 + col2] =
                    h2bits(lrelu(acc[mt][nt][0] + sBla[cc]), lrelu(acc[mt][nt][1] + sBla[cc + 1]));
                sH[(r + 8) * HSTR2 + col2] =
                    h2bits(lrelu(acc[mt][nt][2] + sBla[cc]), lrelu(acc[mt][nt][3] + sBla[cc + 1]));
#pragma unroll
                for (int i = 0; i < 4; i++) acc[mt][nt][i] = 0.f;
            }
        }
        issueW(sb + OFW * 4, gWB + WTILE, tid);                // layer-B W1 -> buf0
        CP_WAIT0();
        __syncthreads();   // H visible + layer-B weights resident

        // ---------------- layer B ----------------
        mmaChunkL(hBase,       HSTR2 * 4, wBase + (uint32_t)WTILE * 4, acc);
        mmaChunkL(hBase + 128, HSTR2 * 4, wBase,                       acc);
        __syncthreads();   // layer-B W buffers free

        if (it < 3) {      // prefetch next phase's first W chunk -> buf0
            int pn = (it + 1) & 1;
            issueW(sb + OFW * 4, g_WAh + (size_t)((pn * NT + t) * NCH_A) * WTILE, tid);
        }
        if (it == 1)       // prefetch next batch's A chunk0 under the gate
            gatherChunk(pA, sites, bonds, bb0 + 1, sE, sI1, sI2, 0, tid);
        if (tid < TM) sRed[tid] = 0.f;
        __syncthreads();

        // ---- gate dot ----
#pragma unroll
        for (int mt = 0; mt < 2; mt++) {
            int r = wm * 32 + mt * 16 + grp;
            float d0 = 0.f, d1 = 0.f;
#pragma unroll
            for (int nt = 0; nt < 4; nt++) {
                int cc = wn * 32 + nt * 8 + 2 * qq;
                float w0 = sWg[cc], w1 = sWg[cc + 1];
                d0 += lrelu(acc[mt][nt][0] + sBlb[cc]) * w0
                    + lrelu(acc[mt][nt][1] + sBlb[cc + 1]) * w1;
                d1 += lrelu(acc[mt][nt][2] + sBlb[cc]) * w0
                    + lrelu(acc[mt][nt][3] + sBlb[cc + 1]) * w1;
            }
            d0 += __shfl_xor_sync(0xffffffffu, d0, 1);
            d0 += __shfl_xor_sync(0xffffffffu, d0, 2);
            d1 += __shfl_xor_sync(0xffffffffu, d1, 1);
            d1 += __shfl_xor_sync(0xffffffffu, d1, 2);
            if (qq == 0) {
                atomicAdd(&sRed[r], d0);
                atomicAdd(&sRed[r + 8], d1);
            }
        }
        __syncthreads();

        // ---- gate apply: p0 park g1 in regs; p1 combine + vector-red scatter ----
#pragma unroll
        for (int mt = 0; mt < 2; mt++) {
            int r = wm * 32 + mt * 16 + grp;
            float sig0 = 1.f / (1.f + __expf(-(sRed[r] + bg)));
            float sig1 = 1.f / (1.f + __expf(-(sRed[r + 8] + bg)));
            if (p == 0) {
#pragma unroll
                for (int nt = 0; nt < 4; nt++) {
                    int cc = wn * 32 + nt * 8 + 2 * qq;
                    int gi = (mt * 4 + nt) * 2;
                    g1h[gi]     = h2bits(sig0 * lrelu(acc[mt][nt][0] + sBlb[cc]),
                                         sig0 * lrelu(acc[mt][nt][1] + sBlb[cc + 1]));
                    g1h[gi + 1] = h2bits(sig1 * lrelu(acc[mt][nt][2] + sBlb[cc]),
                                         sig1 * lrelu(acc[mt][nt][3] + sBlb[cc + 1]));
                }
            } else {
                bool v0 = sE[r] >= 0, v1 = sE[r + 8] >= 0;
                float* d0p = out + ((size_t)bb * NNODE + sI2[r]) * DOUT;
                float* d1p = out + ((size_t)bb * NNODE + sI2[r + 8]) * DOUT;
#pragma unroll
                for (int nt = 0; nt < 4; nt++) {
                    int cc = wn * 32 + nt * 8 + 2 * qq;
                    int gi = (mt * 4 + nt) * 2;
                    float2 ga = h2f2(g1h[gi]);
                    float2 gb = h2f2(g1h[gi + 1]);
                    if (v0) {
                        red2(d0p + cc,
                             sig0 * lrelu(acc[mt][nt][0] + sBlb[cc]) + ga.x,
                             sig0 * lrelu(acc[mt][nt][1] + sBlb[cc + 1]) + ga.y);
                    }
                    if (v1) {
                        red2(d1p + cc,
                             sig1 * lrelu(acc[mt][nt][2] + sBlb[cc]) + gb.x,
                             sig1 * lrelu(acc[mt][nt][3] + sBlb[cc + 1]) + gb.y);
                    }
                }
            }
        }
    } // it
}

// ---------------- launcher ----------------
extern "C" void kernel_launch(void* const* d_in, const int* in_sizes, int n_in,
                              void* d_out, int out_size) {
    (void)in_sizes; (void)n_in;
    const float* sites = (const float*)d_in[0];
    const float* bonds = (const float*)d_in[1];
    const int*   idx1  = (const int*)d_in[2];
    const int*   idx2  = (const int*)d_in[3];
    const int*   uc    = (const int*)d_in[4];
    const float* W1a = (const float*)d_in[5];
    const float* b1a = (const float*)d_in[6];
    const float* W1b = (const float*)d_in[7];
    const float* b1b = (const float*)d_in[8];
    const float* W2a = (const float*)d_in[9];
    const float* b2a = (const float*)d_in[10];
    const float* W2b = (const float*)d_in[11];
    const float* b2b = (const float*)d_in[12];
    const float* Wa1 = (const float*)d_in[13];
    const float* ba1 = (const float*)d_in[14];
    const float* Wa2 = (const float*)d_in[15];
    const float* ba2 = (const float*)d_in[16];
    float* out = (float*)d_out;

    cudaFuncSetAttribute(k_fused, cudaFuncAttributeMaxDynamicSharedMemorySize, SMEM_BYTES);

    k_prep<<<PB_ZERO + PB_HIST + PB_PREPW, 256>>>(out, out_size, uc, W1a, W2a, W1b, W2b);
    k_scan<<<1, 256>>>();
    k_scatter<<<NHB, 256>>>(uc);
    dim3 grid(NTILES, BATCH / 2);
    k_fused<<<grid, TB, SMEM_BYTES>>>(sites, bonds, idx1, idx2,
                                      b1a, b1b, b2a, b2b,
                                      Wa1, ba1, Wa2, ba2, out);
}

// round 9
// speedup vs baseline: 5.0680x; 1.0711x over previous
#include <cuda_runtime.h>
#include <cuda_fp16.h>
#include <cstdint>

// ---------------- problem constants ----------------
#define BATCH 4
#define NNODE 4096
#define NEDGE 65536
#define DIN   128
#define DBOND 64
#define DOUT  128
#define NT    4
#define DCAT  320

#define TM    128
#define TB    512                  // 16 warps
#define NCH_A 5
#define NCH_B 2
#define WSTR2 36
#define WTILE (128*WSTR2)          // 4608 u32
#define ASTR2 36
#define ACH   (TM*ASTR2)           // 4608 u32
#define HSTR2 68
#define NTILES (NEDGE/TM + NT)     // 516
#define NHB   256

#define PB_ZERO 2048
#define PB_HIST NHB
#define PB_PREPW (2*NT*(NCH_A+NCH_B))

// ---------------- device scratch ----------------
__device__ int g_poff[NT + 1];
__device__ __align__(16) int g_bcnt[NHB * NT];
__device__ __align__(16) int g_bbase[NHB * NT];
__device__ __align__(16) int g_order[NEDGE + NT * TM];
__device__ uint32_t g_WAh[2 * NT * NCH_A * WTILE];
__device__ uint32_t g_WBh[2 * NT * NCH_B * WTILE];

// ---------------- helpers ----------------
__device__ __forceinline__ float lrelu(float x) { return x > 0.f ? x : 0.01f * x; }
__device__ __forceinline__ uint32_t h2bits(float a, float b) {
    __half2 h = __floats2half2_rn(a, b);
    return *reinterpret_cast<uint32_t*>(&h);
}
__device__ __forceinline__ float2 h2f2(uint32_t u) {
    __half2 h = *reinterpret_cast<__half2*>(&u);
    return __half22float2(h);
}
__device__ __forceinline__ uint32_t smem_u32(const void* p) {
    uint32_t a;
    asm("{ .reg .u64 t; cvta.to.shared.u64 t, %1; cvt.u32.u64 %0, t; }" : "=r"(a) : "l"(p));
    return a;
}
__device__ __forceinline__ void cpasync16(uint32_t saddr, const void* g) {
    asm volatile("cp.async.ca.shared.global [%0], [%1], 16;" :: "r"(saddr), "l"(g));
}
#define CP_COMMIT() asm volatile("cp.async.commit_group;" ::: "memory")
#define CP_WAIT0()  asm volatile("cp.async.wait_group 0;" ::: "memory")
__device__ __forceinline__ void red2(float* addr, float a, float b) {
    asm volatile("red.global.add.v2.f32 [%0], {%1, %2};" :: "l"(addr), "f"(a), "f"(b) : "memory");
}
__device__ __forceinline__ void ldsm4(uint32_t& r0, uint32_t& r1, uint32_t& r2, uint32_t& r3,
                                      uint32_t addr) {
    asm volatile("ldmatrix.sync.aligned.m8n8.x4.shared.b16 {%0,%1,%2,%3}, [%4];"
        : "=r"(r0), "=r"(r1), "=r"(r2), "=r"(r3) : "r"(addr));
}
__device__ __forceinline__ void mma16(float* d, uint32_t a0, uint32_t a1, uint32_t a2, uint32_t a3,
                                      uint32_t b0, uint32_t b1) {
    asm volatile(
        "mma.sync.aligned.m16n8k16.row.col.f32.f16.f16.f32 "
        "{%0,%1,%2,%3},{%4,%5,%6,%7},{%8,%9},{%0,%1,%2,%3};"
        : "+f"(d[0]), "+f"(d[1]), "+f"(d[2]), "+f"(d[3])
        : "r"(a0), "r"(a1), "r"(a2), "r"(a3), "r"(b0), "r"(b1));
}

// ---------------- prep kernels (unchanged) ----------------
__global__ void k_prep(float* __restrict__ out, int n_out, const int* __restrict__ uc,
                       const float* __restrict__ W1a, const float* __restrict__ W2a,
                       const float* __restrict__ W1b, const float* __restrict__ W2b) {
    __shared__ int cnt[NT];
    __shared__ float smw[64 * 129];
    const int blk = blockIdx.x;
    const int tid = threadIdx.x;

    if (blk < PB_ZERO) {
        int i = blk * 256 + tid;
        if (i < (n_out >> 2)) ((float4*)out)[i] = make_float4(0.f, 0.f, 0.f, 0.f);
        if (i < (NEDGE + NT * TM) / 4) ((int4*)g_order)[i] = make_int4(-1, -1, -1, -1);
        return;
    }
    if (blk < PB_ZERO + PB_HIST) {
        int hb = blk - PB_ZERO;
        if (tid < NT) cnt[tid] = 0;
        __syncthreads();
        atomicAdd(&cnt[uc[hb * 256 + tid]], 1);
        __syncthreads();
        if (tid < NT) g_bcnt[hb * NT + tid] = cnt[tid];
        return;
    }
    int wb = blk - PB_ZERO - PB_HIST;
    bool isA = wb < 2 * NT * NCH_A;
    int c, pt;
    if (isA) { c = wb % NCH_A; pt = wb / NCH_A; }
    else     { int j = wb - 2 * NT * NCH_A; c = j % NCH_B; pt = j / NCH_B; }
    int t = pt & 3, p = pt >> 2;
    int ld = isA ? DCAT : DOUT;
    const float* W = isA ? (p ? W2a : W1a) : (p ? W2b : W1b);
#pragma unroll
    for (int i = 0; i < 32; i++) {
        int lin = tid + 256 * i;
        int k = lin >> 7, n = lin & 127;
        smw[k * 129 + n] = W[((size_t)t * ld + c * 64 + k) * DOUT + n];
    }
    __syncthreads();
    uint32_t* dst = isA ? (g_WAh + (size_t)(pt * NCH_A + c) * WTILE)
                        : (g_WBh + (size_t)(pt * NCH_B + c) * WTILE);
#pragma unroll
    for (int i = 0; i < 16; i++) {
        int lin = tid + 256 * i;
        int n = lin >> 5, k2 = lin & 31;
        dst[n * WSTR2 + k2] = h2bits(smw[(2 * k2) * 129 + n], smw[(2 * k2 + 1) * 129 + n]);
    }
}

__global__ void k_scan() {
    __shared__ int wsum[8][NT];
    __shared__ int tot[NT];
    int tid = threadIdx.x, lane = tid & 31, w = tid >> 5;
    int4 v = ((const int4*)g_bcnt)[tid];
    int4 orig = v;
#pragma unroll
    for (int d = 1; d < 32; d <<= 1) {
        int x = __shfl_up_sync(~0u, v.x, d), y = __shfl_up_sync(~0u, v.y, d);
        int z = __shfl_up_sync(~0u, v.z, d), q = __shfl_up_sync(~0u, v.w, d);
        if (lane >= d) { v.x += x; v.y += y; v.z += z; v.w += q; }
    }
    if (lane == 31) { wsum[w][0] = v.x; wsum[w][1] = v.y; wsum[w][2] = v.z; wsum[w][3] = v.w; }
    __syncthreads();
    if (tid == 0) {
        int a0 = 0, a1 = 0, a2 = 0, a3 = 0;
        for (int i = 0; i < 8; i++) {
            int t0 = wsum[i][0], t1 = wsum[i][1], t2 = wsum[i][2], t3 = wsum[i][3];
            wsum[i][0] = a0; wsum[i][1] = a1; wsum[i][2] = a2; wsum[i][3] = a3;
            a0 += t0; a1 += t1; a2 += t2; a3 += t3;
        }
        tot[0] = a0; tot[1] = a1; tot[2] = a2; tot[3] = a3;
    }
    __syncthreads();
    int e0 = v.x + wsum[w][0] - orig.x;
    int e1 = v.y + wsum[w][1] - orig.y;
    int e2 = v.z + wsum[w][2] - orig.z;
    int e3 = v.w + wsum[w][3] - orig.w;
    int p0 = 0;
    int p1 = p0 + ((tot[0] + TM - 1) / TM) * TM;
    int p2 = p1 + ((tot[1] + TM - 1) / TM) * TM;
    int p3 = p2 + ((tot[2] + TM - 1) / TM) * TM;
    int p4 = p3 + ((tot[3] + TM - 1) / TM) * TM;
    int4 bb; bb.x = p0 + e0; bb.y = p1 + e1; bb.z = p2 + e2; bb.w = p3 + e3;
    ((int4*)g_bbase)[tid] = bb;
    if (tid == 0) {
        g_poff[0] = p0; g_poff[1] = p1; g_poff[2] = p2; g_poff[3] = p3; g_poff[4] = p4;
    }
}

__global__ void k_scatter(const int* __restrict__ uc) {
    __shared__ int base[NT];
    __shared__ int cur[NT];
    int tid = threadIdx.x;
    if (tid < NT) { base[tid] = g_bbase[blockIdx.x * NT + tid]; cur[tid] = 0; }
    __syncthreads();
    int e = blockIdx.x * 256 + tid;
    int t = uc[e];
    int pos = atomicAdd(&cur[t], 1);
    g_order[base[t] + pos] = e;
}

// ---------------- fused kernel smem layout (u32 units) ----------------
#define OFA    0                       // 2 x 4608 (A chunk double buffer)
#define OFW    9216                    // 2 pair-slots x 2 tiles x 4608 = 18432
#define OFH    27648                   // 2 x (128 x 68) = 17408
#define OFRED  45056
#define OFBIAS 45184                   // 6 x 128
#define OFE    45952
#define OFI1   46080
#define OFI2   46208
#define SMEM_U32 46336
#define SMEM_BYTES (SMEM_U32 * 4)      // 185344

__device__ __forceinline__ void issueWpair(uint32_t sdst, const uint32_t* __restrict__ ga,
                                           const uint32_t* __restrict__ gb, int tid) {
    const uint4* g0 = (const uint4*)ga;
    const uint4* g1 = (const uint4*)gb;
#pragma unroll
    for (int i = 0; i < 5; i++) {
        int lin = tid + TB * i;
        if (lin < 1152) {
            cpasync16(sdst + lin * 16, g0 + lin);
            cpasync16(sdst + WTILE * 4 + lin * 16, g1 + lin);
        }
    }
    CP_COMMIT();
}

__device__ __forceinline__ void gatherChunk(float4* pA, const float* __restrict__ sites,
                                            const float* __restrict__ bonds, int b,
                                            const int* sE, const int* sI1, const int* sI2,
                                            int c, int tid) {
#pragma unroll
    for (int i = 0; i < 4; i++) {
        int lin = tid + TB * i;
        int row = lin >> 4, col = (lin & 15) << 2;
        const float* src;
        if (c < 2)      src = sites + ((size_t)b * NNODE + sI1[row]) * DIN + c * 64 + col;
        else if (c < 4) src = sites + ((size_t)b * NNODE + sI2[row]) * DIN + (c - 2) * 64 + col;
        else { int e = sE[row]; if (e < 0) e = 0;
               src = bonds + ((size_t)b * NEDGE + e) * DBOND + col; }
        pA[i] = *(const float4*)src;
    }
}

__device__ __forceinline__ void stageChunk(uint32_t* __restrict__ Ab, const float4* pA, int tid) {
#pragma unroll
    for (int i = 0; i < 4; i++) {
        int lin = tid + TB * i;
        int row = lin >> 4, j = (lin & 15) << 1;
        uint2 v;
        v.x = h2bits(pA[i].x, pA[i].y);
        v.y = h2bits(pA[i].z, pA[i].w);
        *(uint2*)(Ab + row * ASTR2 + j) = v;
    }
}

// merged layer-A chunk: warp tile 32 x 64 over (128 x 256)
__device__ __forceinline__ void mmaMerged(uint32_t aAddr, uint32_t wAddr, float acc[2][8][4]) {
#pragma unroll
    for (int kk = 0; kk < 4; kk++) {
        const uint32_t kb = kk * 32;
        uint32_t bw[16];
        ldsm4(bw[0],  bw[1],  bw[2],  bw[3],  wAddr + kb);
        ldsm4(bw[4],  bw[5],  bw[6],  bw[7],  wAddr + 16 * WSTR2 * 4 + kb);
        ldsm4(bw[8],  bw[9],  bw[10], bw[11], wAddr + 32 * WSTR2 * 4 + kb);
        ldsm4(bw[12], bw[13], bw[14], bw[15], wAddr + 48 * WSTR2 * 4 + kb);
#pragma unroll
        for (int mt = 0; mt < 2; mt++) {
            uint32_t a0, a1, a2, a3;
            ldsm4(a0, a1, a2, a3, aAddr + mt * 16 * ASTR2 * 4 + kb);
#pragma unroll
            for (int nt = 0; nt < 8; nt++)
                mma16(acc[mt][nt], a0, a1, a2, a3, bw[2 * nt], bw[2 * nt + 1]);
        }
    }
}

// layer-B chunk: warp tile 32 x 32
__device__ __forceinline__ void mmaChunkL(uint32_t aAddr, int astrB, uint32_t wAddr,
                                          float acc[2][4][4]) {
#pragma unroll
    for (int kk = 0; kk < 4; kk++) {
        const uint32_t kb = kk * 32;
        uint32_t b00, b01, b10, b11, b20, b21, b30, b31;
        ldsm4(b00, b01, b10, b11, wAddr + kb);
        ldsm4(b20, b21, b30, b31, wAddr + 16 * WSTR2 * 4 + kb);
#pragma unroll
        for (int mt = 0; mt < 2; mt++) {
            uint32_t a0, a1, a2, a3;
            ldsm4(a0, a1, a2, a3, aAddr + mt * 16 * astrB + kb);
            mma16(acc[mt][0], a0, a1, a2, a3, b00, b01);
            mma16(acc[mt][1], a0, a1, a2, a3, b10, b11);
            mma16(acc[mt][2], a0, a1, a2, a3, b20, b21);
            mma16(acc[mt][3], a0, a1, a2, a3, b30, b31);
        }
    }
}

__global__ void __launch_bounds__(TB) k_fused(
    const float* __restrict__ sites, const float* __restrict__ bonds,
    const int* __restrict__ idx1, const int* __restrict__ idx2,
    const float* __restrict__ b1a, const float* __restrict__ b1b,
    const float* __restrict__ b2a, const float* __restrict__ b2b,
    const float* __restrict__ Wa1, const float* __restrict__ ba1,
    const float* __restrict__ Wa2, const float* __restrict__ ba2,
    float* __restrict__ out)
{
    extern __shared__ uint32_t sm[];
    uint32_t* sH0 = sm + OFH;
    uint32_t* sH1 = sm + OFH + 128 * HSTR2;
    float* sRed  = (float*)(sm + OFRED);
    float* sBias = (float*)(sm + OFBIAS);
    int* sE  = (int*)(sm + OFE);
    int* sI1 = (int*)(sm + OFI1);
    int* sI2 = (int*)(sm + OFI2);

    const int tile  = blockIdx.x;
    const int start = tile * TM;
    if (start >= g_poff[NT]) return;
    int t = 0;
#pragma unroll
    for (int i = 1; i < NT; i++) if (start >= g_poff[i]) t = i;

    const int tid  = threadIdx.x;
    const int lane = tid & 31;
    const int wid  = tid >> 5;
    const int wm   = wid & 3;       // 32-row quarter (both layers)
    const int wn   = wid >> 2;      // layer A: 64-col group; layer B: 32-col group
    const int grp  = lane >> 2;
    const int qq   = lane & 3;

    if (tid < TM) {
        int e = g_order[start + tid];
        sE[tid] = e;
        int es = e < 0 ? 0 : e;
        sI1[tid] = idx1[es];
        sI2[tid] = idx2[es];
    }
    if (tid < 128) {
        sBias[0 * 128 + tid] = b1a[t * DOUT + tid];
        sBias[1 * 128 + tid] = b1b[t * DOUT + tid];
        sBias[2 * 128 + tid] = Wa1[tid];
        sBias[3 * 128 + tid] = b2a[t * DOUT + tid];
        sBias[4 * 128 + tid] = b2b[t * DOUT + tid];
        sBias[5 * 128 + tid] = Wa2[tid];
    }
    __syncthreads();

    // ldmatrix lane offsets
    const int rA = wm * 32 + (lane & 7) + ((lane >> 3) & 1) * 8;
    const int nB = (lane & 7) + ((lane >> 4) & 1) * 8;
    const uint32_t sb = smem_u32(sm);
    const uint32_t aBase = sb + (uint32_t)(rA * ASTR2 + (lane >> 4) * 4) * 4;
    const uint32_t hBase0 = sb + (uint32_t)(OFH + rA * HSTR2 + (lane >> 4) * 4) * 4;
    const uint32_t hBase1 = hBase0 + (uint32_t)(128 * HSTR2) * 4;
    // layer A W: pair slot + tile (wn>>1) + col (wn&1)*64
    const uint32_t wBaseA = sb + (uint32_t)(OFW + (wn >> 1) * WTILE
                           + ((wn & 1) * 64 + nB) * WSTR2 + ((lane >> 3) & 1) * 4) * 4;
    // layer B W: pair slot + chunk tile + col wn*32
    const uint32_t wBaseB = sb + (uint32_t)(OFW + (wn * 32 + nB) * WSTR2
                           + ((lane >> 3) & 1) * 4) * 4;
    const uint32_t PAIR = (uint32_t)(2 * WTILE) * 4;   // bytes per pair slot

    const int bb0 = blockIdx.y * 2;
    const float bg1 = ba1[0], bg2 = ba2[0];
    const int phase = wn >> 1;             // layer-A epilogue phase of this warp
    const float* sBlaP = sBias + (phase * 3) * 128;
    uint32_t* sHp = phase ? sH1 : sH0;

    const uint32_t* gWA1 = g_WAh + (size_t)((0 * NT + t) * NCH_A) * WTILE;
    const uint32_t* gWA2 = g_WAh + (size_t)((1 * NT + t) * NCH_A) * WTILE;
    const uint32_t* gWB1 = g_WBh + (size_t)((0 * NT + t) * NCH_B) * WTILE;
    const uint32_t* gWB2 = g_WBh + (size_t)((1 * NT + t) * NCH_B) * WTILE;

    float4 pA[4];
    uint32_t g1h[16];

    // prologue: W chunk0 pair -> slot0; gather A(bb0, c0)
    issueWpair(sb + OFW * 4, gWA1, gWA2, tid);
    gatherChunk(pA, sites, bonds, bb0, sE, sI1, sI2, 0, tid);

#pragma unroll 1
    for (int bb = bb0; bb < bb0 + 2; ++bb) {
        float acc[2][8][4];
#pragma unroll
        for (int mt = 0; mt < 2; mt++)
#pragma unroll
            for (int nt = 0; nt < 8; nt++)
#pragma unroll
                for (int i = 0; i < 4; i++) acc[mt][nt][i] = 0.f;

        // ---------------- merged layer A: [128x320] @ [320x256] ----------------
#pragma unroll
        for (int c = 0; c < NCH_A; c++) {
            const int s = c & 1;
            stageChunk(sm + OFA + s * ACH, pA, tid);
            CP_WAIT0();
            __syncthreads();
            if (c + 1 < NCH_A) {
                issueWpair(sb + OFW * 4 + ((c + 1) & 1) * PAIR,
                           gWA1 + (size_t)(c + 1) * WTILE, gWA2 + (size_t)(c + 1) * WTILE, tid);
                gatherChunk(pA, sites, bonds, bb, sE, sI1, sI2, c + 1, tid);
            } else {
                // layer-B W1b (both chunks) -> pair slot 1
                issueWpair(sb + OFW * 4 + PAIR, gWB1, gWB1 + WTILE, tid);
            }
            mmaMerged(aBase + (uint32_t)(s * ACH) * 4, wBaseA + (s & 1) * PAIR, acc);
        }
        __syncthreads();   // all layer-A MMA done

        // ---- epilogue A: H_phase = fp16(lrelu(acc + bla_phase)) ----
#pragma unroll
        for (int mt = 0; mt < 2; mt++) {
            int r = wm * 32 + mt * 16 + grp;
#pragma unroll
            for (int nt = 0; nt < 8; nt++) {
                int ccl = (wn & 1) * 64 + nt * 8 + 2 * qq;
                int col2 = (wn & 1) * 32 + nt * 4 + qq;
                sHp[r * HSTR2 + col2] =
                    h2bits(lrelu(acc[mt][nt][0] + sBlaP[ccl]), lrelu(acc[mt][nt][1] + sBlaP[ccl + 1]));
                sHp[(r + 8) * HSTR2 + col2] =
                    h2bits(lrelu(acc[mt][nt][2] + sBlaP[ccl]), lrelu(acc[mt][nt][3] + sBlaP[ccl + 1]));
            }
        }
        if (bb == bb0)     // prefetch next batch's A chunk0 under layer B
            gatherChunk(pA, sites, bonds, bb0 + 1, sE, sI1, sI2, 0, tid);
        CP_WAIT0();
        __syncthreads();   // H visible + W1b pair resident

        float acc2[2][4][4];
#pragma unroll
        for (int mt = 0; mt < 2; mt++)
#pragma unroll
            for (int nt = 0; nt < 4; nt++)
#pragma unroll
                for (int i = 0; i < 4; i++) acc2[mt][nt][i] = 0.f;

        // ---------------- layer B, phase 0: out1 = H1 @ W1b ----------------
        mmaChunkL(hBase0,       HSTR2 * 4, wBaseB + PAIR,             acc2);
        mmaChunkL(hBase0 + 128, HSTR2 * 4, wBaseB + PAIR + WTILE * 4, acc2);
        // W2b pair -> slot 0 (slot0's last reads finished before the sync above)
        issueWpair(sb + OFW * 4, gWB2, gWB2 + WTILE, tid);
        __syncthreads();
        if (tid < TM) sRed[tid] = 0.f;
        __syncthreads();
        // gate dot p0
#pragma unroll
        for (int mt = 0; mt < 2; mt++) {
            int r = wm * 32 + mt * 16 + grp;
            float d0 = 0.f, d1 = 0.f;
#pragma unroll
            for (int nt = 0; nt < 4; nt++) {
                int cc = wn * 32 + nt * 8 + 2 * qq;
                float w0 = sBias[2 * 128 + cc], w1 = sBias[2 * 128 + cc + 1];
                d0 += lrelu(acc2[mt][nt][0] + sBias[1 * 128 + cc]) * w0
                    + lrelu(acc2[mt][nt][1] + sBias[1 * 128 + cc + 1]) * w1;
                d1 += lrelu(acc2[mt][nt][2] + sBias[1 * 128 + cc]) * w0
                    + lrelu(acc2[mt][nt][3] + sBias[1 * 128 + cc + 1]) * w1;
            }
            d0 += __shfl_xor_sync(0xffffffffu, d0, 1);
            d0 += __shfl_xor_sync(0xffffffffu, d0, 2);
            d1 += __shfl_xor_sync(0xffffffffu, d1, 1);
            d1 += __shfl_xor_sync(0xffffffffu, d1, 2);
            if (qq == 0) {
                atomicAdd(&sRed[r], d0);
                atomicAdd(&sRed[r + 8], d1);
            }
        }
        CP_WAIT0();        // W2b in flight -> resident before next sync
        __syncthreads();
        // park g1 = sig0 * lrelu(out1 + b1b)  (fp16 pairs)
#pragma unroll
        for (int mt = 0; mt < 2; mt++) {
            int r = wm * 32 + mt * 16 + grp;
            float sig0 = 1.f / (1.f + __expf(-(sRed[r] + bg1)));
            float sig1 = 1.f / (1.f + __expf(-(sRed[r + 8] + bg1)));
#pragma unroll
            for (int nt = 0; nt < 4; nt++) {
                int cc = wn * 32 + nt * 8 + 2 * qq;
                int gi = (mt * 4 + nt) * 2;
                g1h[gi]     = h2bits(sig0 * lrelu(acc2[mt][nt][0] + sBias[1 * 128 + cc]),
                                     sig0 * lrelu(acc2[mt][nt][1] + sBias[1 * 128 + cc + 1]));
                g1h[gi + 1] = h2bits(sig1 * lrelu(acc2[mt][nt][2] + sBias[1 * 128 + cc]),
                                     sig1 * lrelu(acc2[mt][nt][3] + sBias[1 * 128 + cc + 1]));
            }
        }

        // ---------------- layer B, phase 1: out2 = H2 @ W2b ----------------
#pragma unroll
        for (int mt = 0; mt < 2; mt++)
#pragma unroll
            for (int nt = 0; nt < 4; nt++)
#pragma unroll
                for (int i = 0; i < 4; i++) acc2[mt][nt][i] = 0.f;
        mmaChunkL(hBase1,       HSTR2 * 4, wBaseB,             acc2);
        mmaChunkL(hBase1 + 128, HSTR2 * 4, wBaseB + WTILE * 4, acc2);
        __syncthreads();   // out2 mma done; sRed reads done -> safe to reissue + rezero
        if (bb == bb0)     // next batch's layer-A chunk0 pair -> slot0
            issueWpair(sb + OFW * 4, gWA1, gWA2, tid);
        if (tid < TM) sRed[tid] = 0.f;
        __syncthreads();
        // gate dot p1
#pragma unroll
        for (int mt = 0; mt < 2; mt++) {
            int r = wm * 32 + mt * 16 + grp;
            float d0 = 0.f, d1 = 0.f;
#pragma unroll
            for (int nt = 0; nt < 4; nt++) {
                int cc = wn * 32 + nt * 8 + 2 * qq;
                float w0 = sBias[5 * 128 + cc], w1 = sBias[5 * 128 + cc + 1];
                d0 += lrelu(acc2[mt][nt][0] + sBias[4 * 128 + cc]) * w0
                    + lrelu(acc2[mt][nt][1] + sBias[4 * 128 + cc + 1]) * w1;
                d1 += lrelu(acc2[mt][nt][2] + sBias[4 * 128 + cc]) * w0
                    + lrelu(acc2[mt][nt][3] + sBias[4 * 128 + cc + 1]) * w1;
            }
            d0 += __shfl_xor_sync(0xffffffffu, d0, 1);
            d0 += __shfl_xor_sync(0xffffffffu, d0, 2);
            d1 += __shfl_xor_sync(0xffffffffu, d1, 1);
            d1 += __shfl_xor_sync(0xffffffffu, d1, 2);
            if (qq == 0) {
                atomicAdd(&sRed[r], d0);
                atomicAdd(&sRed[r + 8], d1);
            }
        }
        __syncthreads();
        // combine g1 + g2 and scatter
#pragma unroll
        for (int mt = 0; mt < 2; mt++) {
            int r = wm * 32 + mt * 16 + grp;
            float sig0 = 1.f / (1.f + __expf(-(sRed[r] + bg2)));
            float sig1 = 1.f / (1.f + __expf(-(sRed[r + 8] + bg2)));
            bool v0 = sE[r] >= 0, v1 = sE[r + 8] >= 0;
            float* d0p = out + ((size_t)bb * NNODE + sI2[r]) * DOUT;
            float* d1p = out + ((size_t)bb * NNODE + sI2[r + 8]) * DOUT;
#pragma unroll
            for (int nt = 0; nt < 4; nt++) {
                int cc = wn * 32 + nt * 8 + 2 * qq;
                int gi = (mt * 4 + nt) * 2;
                float2 ga = h2f2(g1h[gi]);
                float2 gb = h2f2(g1h[gi + 1]);
                if (v0) {
                    red2(d0p + cc,
                         sig0 * lrelu(acc2[mt][nt][0] + sBias[4 * 128 + cc]) + ga.x,
                         sig0 * lrelu(acc2[mt][nt][1] + sBias[4 * 128 + cc + 1]) + ga.y);
                }
                if (v1) {
                    red2(d1p + cc,
                         sig1 * lrelu(acc2[mt][nt][2] + sBias[4 * 128 + cc]) + gb.x,
                         sig1 * lrelu(acc2[mt][nt][3] + sBias[4 * 128 + cc + 1]) + gb.y);
                }
            }
        }
    } // bb
}

// ---------------- launcher ----------------
extern "C" void kernel_launch(void* const* d_in, const int* in_sizes, int n_in,
                              void* d_out, int out_size) {
    (void)in_sizes; (void)n_in;
    const float* sites = (const float*)d_in[0];
    const float* bonds = (const float*)d_in[1];
    const int*   idx1  = (const int*)d_in[2];
    const int*   idx2  = (const int*)d_in[3];
    const int*   uc    = (const int*)d_in[4];
    const float* W1a = (const float*)d_in[5];
    const float* b1a = (const float*)d_in[6];
    const float* W1b = (const float*)d_in[7];
    const float* b1b = (const float*)d_in[8];
    const float* W2a = (const float*)d_in[9];
    const float* b2a = (const float*)d_in[10];
    const float* W2b = (const float*)d_in[11];
    const float* b2b = (const float*)d_in[12];
    const float* Wa1 = (const float*)d_in[13];
    const float* ba1 = (const float*)d_in[14];
    const float* Wa2 = (const float*)d_in[15];
    const float* ba2 = (const float*)d_in[16];
    float* out = (float*)d_out;

    cudaFuncSetAttribute(k_fused, cudaFuncAttributeMaxDynamicSharedMemorySize, SMEM_BYTES);

    k_prep<<<PB_ZERO + PB_HIST + PB_PREPW, 256>>>(out, out_size, uc, W1a, W2a, W1b, W2b);
    k_scan<<<1, 256>>>();
    k_scatter<<<NHB, 256>>>(uc);
    dim3 grid(NTILES, BATCH / 2);
    k_fused<<<grid, TB, SMEM_BYTES>>>(sites, bonds, idx1, idx2,
                                      b1a, b1b, b2a, b2b,
                                      Wa1, ba1, Wa2, ba2, out);
}